// round 5
// baseline (speedup 1.0000x reference)
#include <cuda_runtime.h>
#include <cstdint>

// ----------------------------------------------------------------------------
// Problem constants
// ----------------------------------------------------------------------------
#define Bc   4
#define Sc   2048
#define Dc   768
#define Hc   12
#define HDc  64
#define Mrows (Bc * Sc)   // 8192

// Scratch (device globals; all tf32-rounded)
__device__ float g_q [(size_t)Mrows * Dc];
__device__ float g_k [(size_t)Mrows * Dc];
__device__ float g_v [(size_t)Mrows * Dc];
__device__ float g_hs[(size_t)Mrows * Dc];
__device__ float g_lq[(size_t)Mrows * Dc];
__device__ float g_lk[(size_t)Mrows * Dc];
__device__ float g_wq[(size_t)Dc * Dc];
__device__ float g_wk[(size_t)Dc * Dc];
__device__ float g_wv[(size_t)Dc * Dc];

// ----------------------------------------------------------------------------
// Helpers
// ----------------------------------------------------------------------------
__device__ __forceinline__ uint32_t tf32r(float x) {
    uint32_t u;
    asm("cvt.rna.tf32.f32 %0, %1;" : "=r"(u) : "f"(x));
    return u;
}
__device__ __forceinline__ float ftf32(float x) { return __uint_as_float(tf32r(x)); }

__device__ __forceinline__ uint32_t smem_u32(const void* p) {
    uint32_t a;
    asm("{ .reg .u64 t; cvta.to.shared.u64 t, %1; cvt.u32.u64 %0, t; }" : "=r"(a) : "l"(p));
    return a;
}
__device__ __forceinline__ void cpa16(uint32_t dst, const void* src) {
    asm volatile("cp.async.cg.shared.global [%0], [%1], 16;" :: "r"(dst), "l"(src));
}
#define CPA_COMMIT() asm volatile("cp.async.commit_group;" ::: "memory")
#define CPA_WAIT(N)  asm volatile("cp.async.wait_group %0;" :: "n"(N) : "memory")

// d += a @ b  (m16n8k8, tf32 inputs, f32 accum)
__device__ __forceinline__ void mma8(float* d, const uint32_t* a, const uint32_t* b) {
    asm volatile(
        "mma.sync.aligned.m16n8k8.row.col.f32.tf32.tf32.f32 "
        "{%0,%1,%2,%3}, {%4,%5,%6,%7}, {%8,%9}, {%0,%1,%2,%3};\n"
        : "+f"(d[0]), "+f"(d[1]), "+f"(d[2]), "+f"(d[3])
        : "r"(a[0]), "r"(a[1]), "r"(a[2]), "r"(a[3]), "r"(b[0]), "r"(b[1]));
}

// ----------------------------------------------------------------------------
// Prep: tf32-round an array (float4 grid-stride)
// ----------------------------------------------------------------------------
__global__ void round_tf32(const float* __restrict__ s, float* __restrict__ d, int n4) {
    int i = blockIdx.x * blockDim.x + threadIdx.x;
    int stride = gridDim.x * blockDim.x;
    for (; i < n4; i += stride) {
        float4 v = ((const float4*)s)[i];
        v.x = ftf32(v.x); v.y = ftf32(v.y); v.z = ftf32(v.z); v.w = ftf32(v.w);
        ((float4*)d)[i] = v;
    }
}

// ----------------------------------------------------------------------------
// Linear: Y = X @ W^T + b  (tf32 mma.sync, 128x128x32 tiles, 2-stage cp.async)
// 8 warps (4x2), warp tile 32x64. Inputs pre-rounded; output stored rounded.
// ----------------------------------------------------------------------------
#define LPAD 36
#define LIN_STAGE_F (128 * LPAD)                 // 4608 floats per matrix per stage
#define LIN_SMEM (4 * LIN_STAGE_F * (int)sizeof(float))   // 73728 B

__global__ __launch_bounds__(256, 2) void linear_tc(
    const float* __restrict__ bq,
    const float* __restrict__ bk,
    const float* __restrict__ bv)
{
    extern __shared__ __align__(16) float sm[];
    float* As[2] = { sm,                  sm + 2 * LIN_STAGE_F };
    float* Bs[2] = { sm + LIN_STAGE_F,    sm + 3 * LIN_STAGE_F };

    const int z = blockIdx.z;
    const float* X    = g_hs;
    const float* W    = (z == 0) ? g_wq : (z == 1) ? g_wk : g_wv;
    const float* bias = (z == 0) ? bq   : (z == 1) ? bk   : bv;
    float* Y          = (z == 0) ? g_q  : (z == 1) ? g_k  : g_v;

    const int tid = threadIdx.x;
    const int wid = tid >> 5, lane = tid & 31;
    const int g = lane >> 2, tig = lane & 3;
    const int warpm = wid >> 1, warpn = wid & 1;
    const int bm = blockIdx.y * 128, bn = blockIdx.x * 128;

    const int crow = tid >> 2, cch = (tid & 3) << 1;  // 4 chunk-pairs per thread

    auto issue = [&](int it, int s) {
        const int k0 = it * 32;
        uint32_t ab = smem_u32(As[s]);
        uint32_t bb = smem_u32(Bs[s]);
        // 128 rows x 8 chunks (16B); thread handles rows crow, crow+64; chunks cch, cch+1
#pragma unroll
        for (int rr = 0; rr < 2; rr++) {
            int row = crow + rr * 64;
#pragma unroll
            for (int cc = 0; cc < 2; cc++) {
                int ch = cch + cc;
                uint32_t off = (uint32_t)(row * LPAD + ch * 4) * 4;
                cpa16(ab + off, X + (size_t)(bm + row) * Dc + k0 + ch * 4);
                cpa16(bb + off, W + (size_t)(bn + row) * Dc + k0 + ch * 4);
            }
        }
        CPA_COMMIT();
    };

    float acc[2][8][4];
#pragma unroll
    for (int mt = 0; mt < 2; mt++)
#pragma unroll
        for (int nt = 0; nt < 8; nt++)
#pragma unroll
            for (int c = 0; c < 4; c++) acc[mt][nt][c] = 0.0f;

    issue(0, 0);
    for (int it = 0; it < 24; it++) {
        const int s = it & 1;
        if (it < 23) issue(it + 1, s ^ 1);
        if (it < 23) { CPA_WAIT(1); } else { CPA_WAIT(0); }
        __syncthreads();

        const float* A = As[s];
        const float* B = Bs[s];
#pragma unroll
        for (int kc = 0; kc < 4; kc++) {
            const int kk = kc * 8;
            uint32_t a[2][4], bfr[8][2];
#pragma unroll
            for (int mt = 0; mt < 2; mt++) {
                int row = warpm * 32 + mt * 16;
                a[mt][0] = __float_as_uint(A[(row + g)     * LPAD + kk + tig]);
                a[mt][1] = __float_as_uint(A[(row + g + 8) * LPAD + kk + tig]);
                a[mt][2] = __float_as_uint(A[(row + g)     * LPAD + kk + tig + 4]);
                a[mt][3] = __float_as_uint(A[(row + g + 8) * LPAD + kk + tig + 4]);
            }
#pragma unroll
            for (int nt = 0; nt < 8; nt++) {
                int col = warpn * 64 + nt * 8;
                bfr[nt][0] = __float_as_uint(B[(col + g) * LPAD + kk + tig]);
                bfr[nt][1] = __float_as_uint(B[(col + g) * LPAD + kk + tig + 4]);
            }
#pragma unroll
            for (int mt = 0; mt < 2; mt++)
#pragma unroll
                for (int nt = 0; nt < 8; nt++)
                    mma8(acc[mt][nt], a[mt], bfr[nt]);
        }
        __syncthreads();
    }

    // Epilogue: bias + tf32-round + store
#pragma unroll
    for (int mt = 0; mt < 2; mt++) {
        const int row0 = bm + warpm * 32 + mt * 16 + g;
#pragma unroll
        for (int nt = 0; nt < 8; nt++) {
            const int col = bn + warpn * 64 + nt * 8 + 2 * tig;
            const float bx = bias[col], by = bias[col + 1];
            *(float2*)&Y[(size_t)row0 * Dc + col] =
                make_float2(ftf32(acc[mt][nt][0] + bx), ftf32(acc[mt][nt][1] + by));
            *(float2*)&Y[(size_t)(row0 + 8) * Dc + col] =
                make_float2(ftf32(acc[mt][nt][2] + bx), ftf32(acc[mt][nt][3] + by));
        }
    }
}

// ----------------------------------------------------------------------------
// Flash attention (tf32 mma.sync), all-M warp layout, P in registers.
// CTA = (b, h, 128-query tile), 256 threads = 8 warps x 16 q-rows each.
// k-tile = 64 keys, double-buffered via cp.async.
// smem floats: QS[128x132], KS[2][64x132], VS[2][64x72], MS[2][64].
// ----------------------------------------------------------------------------
#define KT 64
#define S_QS 0
#define S_KS 16896                 // + s*8448
#define S_VS (16896 + 16896)       // 33792, + s*4608
#define S_MS (33792 + 9216)        // 43008, + s*64
#define ATT_F (43008 + 128)        // 43136 floats
#define ATT_SMEM (ATT_F * (int)sizeof(float))   // 172544 B

__global__ __launch_bounds__(256, 1) void attn_tc(
    const float* __restrict__ mask,
    float* __restrict__ out)
{
    extern __shared__ __align__(16) float sm[];
    const uint32_t smb = smem_u32(sm);

    const int tid = threadIdx.x;
    const int wid = tid >> 5, lane = tid & 31;
    const int g = lane >> 2, tig = lane & 3;

    const int b = blockIdx.z, h = blockIdx.y, q0 = blockIdx.x * 128;
    const int hoff = h * HDc;

    auto issue_tile = [&](int t, int s) {
        const size_t rb = (size_t)(b * Sc + t * KT) * Dc + hoff;
        const float* gk  = g_k  + rb;
        const float* glk = g_lk + rb;
        const float* gv  = g_v  + rb;
        const uint32_t ksb = smb + (uint32_t)(S_KS + s * 8448) * 4;
        const uint32_t vsb = smb + (uint32_t)(S_VS + s * 4608) * 4;
        // KS: 64 rows x 32 chunks (dims 0-63 from k, 64-127 from lk)
#pragma unroll
        for (int i = 0; i < 8; i++) {
            int id = tid + i * 256;
            int row = id >> 5, ch = id & 31;
            const float* src = (ch < 16) ? (gk + (size_t)row * Dc + ch * 4)
                                         : (glk + (size_t)row * Dc + (ch - 16) * 4);
            cpa16(ksb + (uint32_t)(row * 132 + ch * 4) * 4, src);
        }
        // VS: 64 rows x 16 chunks
#pragma unroll
        for (int i = 0; i < 4; i++) {
            int id = tid + i * 256;
            int row = id >> 4, ch = id & 15;
            cpa16(vsb + (uint32_t)(row * 72 + ch * 4) * 4, gv + (size_t)row * Dc + ch * 4);
        }
        // MS: 64 floats
        if (tid < 16)
            cpa16(smb + (uint32_t)(S_MS + s * 64 + tid * 4) * 4,
                  mask + (size_t)b * Sc + t * KT + tid * 4);
        CPA_COMMIT();
    };

    // ---- Q prologue: QS[128x132] (dims 0-63 q, 64-127 lq), group 0
    {
        const size_t rb = (size_t)(b * Sc + q0) * Dc + hoff;
#pragma unroll
        for (int i = 0; i < 16; i++) {
            int id = tid + i * 256;
            int row = id >> 5, ch = id & 31;
            const float* src = (ch < 16) ? (g_q + rb + (size_t)row * Dc + ch * 4)
                                         : (g_lq + rb + (size_t)row * Dc + (ch - 16) * 4);
            cpa16(smb + (uint32_t)(S_QS + row * 132 + ch * 4) * 4, src);
        }
        CPA_COMMIT();
    }
    issue_tile(0, 0);

    float m0 = -1e30f, m1 = -1e30f, l0 = 0.0f, l1 = 0.0f;
    float oacc[8][4];
#pragma unroll
    for (int nt = 0; nt < 8; nt++)
#pragma unroll
        for (int c = 0; c < 4; c++) oacc[nt][c] = 0.0f;

    const float* Qw = sm + S_QS + (wid * 16) * 132;
    const int srcA = (lane & ~3) | (tig >> 1);
    const int srcB = srcA + 2;

    for (int t = 0; t < Sc / KT; t++) {
        const int s = t & 1;
        if (t < Sc / KT - 1) issue_tile(t + 1, s ^ 1);
        if (t < Sc / KT - 1) { CPA_WAIT(1); } else { CPA_WAIT(0); }
        __syncthreads();

        const float* Ks = sm + S_KS + s * 8448;
        const float* Vs = sm + S_VS + s * 4608;
        const float* ms = sm + S_MS + s * 64;

        // ---- QK: sacc[nt] = Q(16 rows) x K(64 keys), k-dim 128
        float sacc[8][4];
#pragma unroll
        for (int nt = 0; nt < 8; nt++)
#pragma unroll
            for (int c = 0; c < 4; c++) sacc[nt][c] = 0.0f;

#pragma unroll
        for (int kc = 0; kc < 16; kc++) {
            const int kk = kc * 8;
            uint32_t a[4];
            a[0] = __float_as_uint(Qw[(g)     * 132 + kk + tig]);
            a[1] = __float_as_uint(Qw[(g + 8) * 132 + kk + tig]);
            a[2] = __float_as_uint(Qw[(g)     * 132 + kk + tig + 4]);
            a[3] = __float_as_uint(Qw[(g + 8) * 132 + kk + tig + 4]);
#pragma unroll
            for (int nt = 0; nt < 8; nt++) {
                uint32_t bfr[2];
                bfr[0] = __float_as_uint(Ks[(nt * 8 + g) * 132 + kk + tig]);
                bfr[1] = __float_as_uint(Ks[(nt * 8 + g) * 132 + kk + tig + 4]);
                mma8(sacc[nt], a, bfr);
            }
        }

        // ---- softmax (rows g and g+8 of this warp's 16-row tile; quad reductions)
        float mx0 = -1e30f, mx1 = -1e30f;
#pragma unroll
        for (int nt = 0; nt < 8; nt++) {
            const float mk0 = ms[nt * 8 + 2 * tig], mk1 = ms[nt * 8 + 2 * tig + 1];
            sacc[nt][0] = sacc[nt][0] * 0.125f + mk0;
            sacc[nt][1] = sacc[nt][1] * 0.125f + mk1;
            sacc[nt][2] = sacc[nt][2] * 0.125f + mk0;
            sacc[nt][3] = sacc[nt][3] * 0.125f + mk1;
            mx0 = fmaxf(mx0, fmaxf(sacc[nt][0], sacc[nt][1]));
            mx1 = fmaxf(mx1, fmaxf(sacc[nt][2], sacc[nt][3]));
        }
        mx0 = fmaxf(mx0, __shfl_xor_sync(0xffffffffu, mx0, 1));
        mx0 = fmaxf(mx0, __shfl_xor_sync(0xffffffffu, mx0, 2));
        mx1 = fmaxf(mx1, __shfl_xor_sync(0xffffffffu, mx1, 1));
        mx1 = fmaxf(mx1, __shfl_xor_sync(0xffffffffu, mx1, 2));

        const float mn0 = fmaxf(m0, mx0), mn1 = fmaxf(m1, mx1);
        const float al0 = __expf(m0 - mn0), al1 = __expf(m1 - mn1);
        float s0 = 0.0f, s1 = 0.0f;
#pragma unroll
        for (int nt = 0; nt < 8; nt++) {
            float p0 = __expf(sacc[nt][0] - mn0);
            float p1 = __expf(sacc[nt][1] - mn0);
            float p2 = __expf(sacc[nt][2] - mn1);
            float p3 = __expf(sacc[nt][3] - mn1);
            s0 += p0 + p1; s1 += p2 + p3;
            sacc[nt][0] = __uint_as_float(tf32r(p0));
            sacc[nt][1] = __uint_as_float(tf32r(p1));
            sacc[nt][2] = __uint_as_float(tf32r(p2));
            sacc[nt][3] = __uint_as_float(tf32r(p3));
        }
        s0 += __shfl_xor_sync(0xffffffffu, s0, 1);
        s0 += __shfl_xor_sync(0xffffffffu, s0, 2);
        s1 += __shfl_xor_sync(0xffffffffu, s1, 1);
        s1 += __shfl_xor_sync(0xffffffffu, s1, 2);
        l0 = l0 * al0 + s0;  l1 = l1 * al1 + s1;
        m0 = mn0;  m1 = mn1;

#pragma unroll
        for (int nt = 0; nt < 8; nt++) {
            oacc[nt][0] *= al0; oacc[nt][1] *= al0;
            oacc[nt][2] *= al1; oacc[nt][3] *= al1;
        }

        // ---- PV: O += P @ V   (P: C-layout -> A-layout via quad shuffles)
#pragma unroll
        for (int kb = 0; kb < 8; kb++) {
            const float p0 = sacc[kb][0], p1 = sacc[kb][1];
            const float p2 = sacc[kb][2], p3 = sacc[kb][3];
            const float x0 = __shfl_sync(0xffffffffu, p0, srcA);
            const float x1 = __shfl_sync(0xffffffffu, p1, srcA);
            const float y0 = __shfl_sync(0xffffffffu, p2, srcA);
            const float y1 = __shfl_sync(0xffffffffu, p3, srcA);
            const float z0 = __shfl_sync(0xffffffffu, p0, srcB);
            const float z1 = __shfl_sync(0xffffffffu, p1, srcB);
            const float w0 = __shfl_sync(0xffffffffu, p2, srcB);
            const float w1 = __shfl_sync(0xffffffffu, p3, srcB);
            uint32_t aa[4];
            aa[0] = __float_as_uint((tig & 1) ? x1 : x0);
            aa[1] = __float_as_uint((tig & 1) ? y1 : y0);
            aa[2] = __float_as_uint((tig & 1) ? z1 : z0);
            aa[3] = __float_as_uint((tig & 1) ? w1 : w0);
#pragma unroll
            for (int nt = 0; nt < 8; nt++) {
                uint32_t bfr[2];
                bfr[0] = __float_as_uint(Vs[(kb * 8 + tig)     * 72 + nt * 8 + g]);
                bfr[1] = __float_as_uint(Vs[(kb * 8 + tig + 4) * 72 + nt * 8 + g]);
                mma8(oacc[nt], aa, bfr);
            }
        }
        __syncthreads();
    }

    // ---- epilogue
    const float i0 = 1.0f / l0, i1 = 1.0f / l1;
    const int row = b * Sc + q0 + wid * 16 + g;
    float* ob = out + (size_t)row * Dc + hoff;
#pragma unroll
    for (int nt = 0; nt < 8; nt++) {
        const int col = nt * 8 + 2 * tig;
        *(float2*)&ob[col] = make_float2(oacc[nt][0] * i0, oacc[nt][1] * i0);
        *(float2*)&ob[(size_t)8 * Dc + col] = make_float2(oacc[nt][2] * i1, oacc[nt][3] * i1);
    }
}

// ----------------------------------------------------------------------------
// Launch
// ----------------------------------------------------------------------------
extern "C" void kernel_launch(void* const* d_in, const int* in_sizes, int n_in,
                              void* d_out, int out_size)
{
    const float* hs   = (const float*)d_in[0];
    const float* lq   = (const float*)d_in[1];
    const float* lk   = (const float*)d_in[2];
    const float* mask = (const float*)d_in[3];
    const float* Wq   = (const float*)d_in[4];
    const float* bq   = (const float*)d_in[5];
    const float* Wk   = (const float*)d_in[6];
    const float* bk   = (const float*)d_in[7];
    const float* Wv   = (const float*)d_in[8];
    const float* bv   = (const float*)d_in[9];
    float* out = (float*)d_out;

    float *p_hs, *p_lq, *p_lk, *p_wq, *p_wk, *p_wv;
    cudaGetSymbolAddress((void**)&p_hs, g_hs);
    cudaGetSymbolAddress((void**)&p_lq, g_lq);
    cudaGetSymbolAddress((void**)&p_lk, g_lk);
    cudaGetSymbolAddress((void**)&p_wq, g_wq);
    cudaGetSymbolAddress((void**)&p_wk, g_wk);
    cudaGetSymbolAddress((void**)&p_wv, g_wv);

    const int nBig = (Mrows * Dc) / 4;      // 1572864
    const int nW   = (Dc * Dc) / 4;         // 147456
    round_tf32<<<1024, 256>>>(hs, p_hs, nBig);
    round_tf32<<<1024, 256>>>(lq, p_lq, nBig);
    round_tf32<<<1024, 256>>>(lk, p_lk, nBig);
    round_tf32<<<256, 256>>>(Wq, p_wq, nW);
    round_tf32<<<256, 256>>>(Wk, p_wk, nW);
    round_tf32<<<256, 256>>>(Wv, p_wv, nW);

    cudaFuncSetAttribute(linear_tc, cudaFuncAttributeMaxDynamicSharedMemorySize, LIN_SMEM);
    dim3 gl(Dc / 128, Mrows / 128, 3);   // (6, 64, 3)
    linear_tc<<<gl, 256, LIN_SMEM>>>(bq, bk, bv);

    cudaFuncSetAttribute(attn_tc, cudaFuncAttributeMaxDynamicSharedMemorySize, ATT_SMEM);
    dim3 ga(Sc / 128, Hc, Bc);           // (16, 12, 4)
    attn_tc<<<ga, 256, ATT_SMEM>>>(mask, out);
}

// round 6
// speedup vs baseline: 1.0876x; 1.0876x over previous
#include <cuda_runtime.h>
#include <cstdint>

// ----------------------------------------------------------------------------
// Problem constants
// ----------------------------------------------------------------------------
#define Bc   4
#define Sc   2048
#define Dc   768
#define Hc   12
#define HDc  64
#define Mrows (Bc * Sc)   // 8192

// Scratch (device globals; all tf32-rounded)
__device__ float g_q [(size_t)Mrows * Dc];
__device__ float g_k [(size_t)Mrows * Dc];
__device__ float g_v [(size_t)Mrows * Dc];
__device__ float g_hs[(size_t)Mrows * Dc];
__device__ float g_lq[(size_t)Mrows * Dc];
__device__ float g_lk[(size_t)Mrows * Dc];
__device__ float g_wq[(size_t)Dc * Dc];
__device__ float g_wk[(size_t)Dc * Dc];
__device__ float g_wv[(size_t)Dc * Dc];

// ----------------------------------------------------------------------------
// Helpers
// ----------------------------------------------------------------------------
__device__ __forceinline__ uint32_t tf32r(float x) {
    uint32_t u;
    asm("cvt.rna.tf32.f32 %0, %1;" : "=r"(u) : "f"(x));
    return u;
}
__device__ __forceinline__ float ftf32(float x) { return __uint_as_float(tf32r(x)); }

__device__ __forceinline__ uint32_t smem_u32(const void* p) {
    uint32_t a;
    asm("{ .reg .u64 t; cvta.to.shared.u64 t, %1; cvt.u32.u64 %0, t; }" : "=r"(a) : "l"(p));
    return a;
}
__device__ __forceinline__ void cpa16(uint32_t dst, const void* src) {
    asm volatile("cp.async.cg.shared.global [%0], [%1], 16;" :: "r"(dst), "l"(src));
}
#define CPA_COMMIT() asm volatile("cp.async.commit_group;" ::: "memory")
#define CPA_WAIT(N)  asm volatile("cp.async.wait_group %0;" :: "n"(N) : "memory")

// ldmatrix x4 on 32-bit data: each 8x4-tf32 block distributes as [l/4][l%4]
__device__ __forceinline__ void ldsm4(uint32_t& r0, uint32_t& r1, uint32_t& r2, uint32_t& r3,
                                      uint32_t addr) {
    asm volatile("ldmatrix.sync.aligned.m8n8.x4.shared.b16 {%0,%1,%2,%3}, [%4];"
                 : "=r"(r0), "=r"(r1), "=r"(r2), "=r"(r3) : "r"(addr));
}

// d += a @ b  (m16n8k8, tf32 inputs, f32 accum)
__device__ __forceinline__ void mma8(float* d, const uint32_t* a, const uint32_t* b) {
    asm volatile(
        "mma.sync.aligned.m16n8k8.row.col.f32.tf32.tf32.f32 "
        "{%0,%1,%2,%3}, {%4,%5,%6,%7}, {%8,%9}, {%0,%1,%2,%3};\n"
        : "+f"(d[0]), "+f"(d[1]), "+f"(d[2]), "+f"(d[3])
        : "r"(a[0]), "r"(a[1]), "r"(a[2]), "r"(a[3]), "r"(b[0]), "r"(b[1]));
}

// ----------------------------------------------------------------------------
// Prep: tf32-round an array (float4 grid-stride)
// ----------------------------------------------------------------------------
__global__ void round_tf32(const float* __restrict__ s, float* __restrict__ d, int n4) {
    int i = blockIdx.x * blockDim.x + threadIdx.x;
    int stride = gridDim.x * blockDim.x;
    for (; i < n4; i += stride) {
        float4 v = ((const float4*)s)[i];
        v.x = ftf32(v.x); v.y = ftf32(v.y); v.z = ftf32(v.z); v.w = ftf32(v.w);
        ((float4*)d)[i] = v;
    }
}

// ----------------------------------------------------------------------------
// Linear: Y = X @ W^T + b  (tf32 mma.sync + ldmatrix, 128x128x32, cp.async x2)
// 8 warps (4x2), warp tile 32x64.
// ----------------------------------------------------------------------------
#define LPAD 36
#define LIN_STAGE_F (128 * LPAD)
#define LIN_SMEM (4 * LIN_STAGE_F * (int)sizeof(float))   // 73728 B

__global__ __launch_bounds__(256, 2) void linear_tc(
    const float* __restrict__ bq,
    const float* __restrict__ bk,
    const float* __restrict__ bv)
{
    extern __shared__ __align__(16) float sm[];
    float* As[2] = { sm,               sm + 2 * LIN_STAGE_F };
    float* Bs[2] = { sm + LIN_STAGE_F, sm + 3 * LIN_STAGE_F };

    const int z = blockIdx.z;
    const float* X    = g_hs;
    const float* W    = (z == 0) ? g_wq : (z == 1) ? g_wk : g_wv;
    const float* bias = (z == 0) ? bq   : (z == 1) ? bk   : bv;
    float* Y          = (z == 0) ? g_q  : (z == 1) ? g_k  : g_v;

    const int tid = threadIdx.x;
    const int wid = tid >> 5, lane = tid & 31;
    const int g = lane >> 2, tig = lane & 3;
    const int warpm = wid >> 1, warpn = wid & 1;
    const int bm = blockIdx.y * 128, bn = blockIdx.x * 128;

    const int crow = tid >> 2, cch = (tid & 3) << 1;

    auto issue = [&](int it, int s) {
        const int k0 = it * 32;
        uint32_t ab = smem_u32(As[s]);
        uint32_t bb = smem_u32(Bs[s]);
#pragma unroll
        for (int rr = 0; rr < 2; rr++) {
            int row = crow + rr * 64;
#pragma unroll
            for (int cc = 0; cc < 2; cc++) {
                int ch = cch + cc;
                uint32_t off = (uint32_t)(row * LPAD + ch * 4) * 4;
                cpa16(ab + off, X + (size_t)(bm + row) * Dc + k0 + ch * 4);
                cpa16(bb + off, W + (size_t)(bn + row) * Dc + k0 + ch * 4);
            }
        }
        CPA_COMMIT();
    };

    float acc[2][8][4];
#pragma unroll
    for (int mt = 0; mt < 2; mt++)
#pragma unroll
        for (int nt = 0; nt < 8; nt++)
#pragma unroll
            for (int c = 0; c < 4; c++) acc[mt][nt][c] = 0.0f;

    // lane-local ldmatrix address components
    const uint32_t a_lrow = (uint32_t)(warpm * 32 + (lane & 15)) * LPAD + ((lane >> 4) << 2);
    const uint32_t b_lrow = (uint32_t)(warpn * 64 + (lane & 7))  * LPAD + ((lane >> 3) << 2);

    issue(0, 0);
    for (int it = 0; it < 24; it++) {
        const int s = it & 1;
        if (it < 23) issue(it + 1, s ^ 1);
        if (it < 23) { CPA_WAIT(1); } else { CPA_WAIT(0); }
        __syncthreads();

        const uint32_t ab = smem_u32(As[s]) + (a_lrow << 2);
        const uint32_t bb = smem_u32(Bs[s]) + (b_lrow << 2);

#pragma unroll
        for (int kc2 = 0; kc2 < 2; kc2++) {
            uint32_t afr[2][2][4];   // [mt][kc-within-pair][4]
#pragma unroll
            for (int mt = 0; mt < 2; mt++)
#pragma unroll
                for (int kl = 0; kl < 2; kl++)
                    ldsm4(afr[mt][kl][0], afr[mt][kl][1], afr[mt][kl][2], afr[mt][kl][3],
                          ab + ((uint32_t)(mt * 16 * LPAD + (kc2 * 2 + kl) * 8) << 2));
#pragma unroll
            for (int nt = 0; nt < 8; nt++) {
                uint32_t m0, m1, m2, m3;
                ldsm4(m0, m1, m2, m3, bb + ((uint32_t)(nt * 8 * LPAD + kc2 * 16) << 2));
                uint32_t b01[2] = {m0, m1}, b23[2] = {m2, m3};
#pragma unroll
                for (int mt = 0; mt < 2; mt++) {
                    mma8(acc[mt][nt], afr[mt][0], b01);
                    mma8(acc[mt][nt], afr[mt][1], b23);
                }
            }
        }
        __syncthreads();
    }

    // Epilogue: bias + tf32-round + store
#pragma unroll
    for (int mt = 0; mt < 2; mt++) {
        const int row0 = bm + warpm * 32 + mt * 16 + g;
#pragma unroll
        for (int nt = 0; nt < 8; nt++) {
            const int col = bn + warpn * 64 + nt * 8 + 2 * tig;
            const float bx = bias[col], by = bias[col + 1];
            *(float2*)&Y[(size_t)row0 * Dc + col] =
                make_float2(ftf32(acc[mt][nt][0] + bx), ftf32(acc[mt][nt][1] + by));
            *(float2*)&Y[(size_t)(row0 + 8) * Dc + col] =
                make_float2(ftf32(acc[mt][nt][2] + bx), ftf32(acc[mt][nt][3] + by));
        }
    }
}

// ----------------------------------------------------------------------------
// Flash attention (tf32 mma.sync), all-M layout, Q in registers, ldmatrix K.
// CTA = (b, h, 128-query tile), 256 threads = 8 warps x 16 q-rows each.
// k-tile = 64 keys, double-buffered cp.async.
// ----------------------------------------------------------------------------
#define KT 64
#define S_QS 0
#define S_KS 16896                 // + s*8448
#define S_VS (16896 + 16896)       // 33792, + s*4608
#define S_MS (33792 + 9216)        // 43008, + s*64
#define ATT_F (43008 + 128)
#define ATT_SMEM (ATT_F * (int)sizeof(float))   // 172544 B

__global__ __launch_bounds__(256, 1) void attn_tc(
    const float* __restrict__ mask,
    float* __restrict__ out)
{
    extern __shared__ __align__(16) float sm[];
    const uint32_t smb = smem_u32(sm);

    const int tid = threadIdx.x;
    const int wid = tid >> 5, lane = tid & 31;
    const int g = lane >> 2, tig = lane & 3;

    const int b = blockIdx.z, h = blockIdx.y, q0 = blockIdx.x * 128;
    const int hoff = h * HDc;

    auto issue_tile = [&](int t, int s) {
        const size_t rb = (size_t)(b * Sc + t * KT) * Dc + hoff;
        const float* gk  = g_k  + rb;
        const float* glk = g_lk + rb;
        const float* gv  = g_v  + rb;
        const uint32_t ksb = smb + (uint32_t)(S_KS + s * 8448) * 4;
        const uint32_t vsb = smb + (uint32_t)(S_VS + s * 4608) * 4;
#pragma unroll
        for (int i = 0; i < 8; i++) {
            int id = tid + i * 256;
            int row = id >> 5, ch = id & 31;
            const float* src = (ch < 16) ? (gk + (size_t)row * Dc + ch * 4)
                                         : (glk + (size_t)row * Dc + (ch - 16) * 4);
            cpa16(ksb + (uint32_t)(row * 132 + ch * 4) * 4, src);
        }
#pragma unroll
        for (int i = 0; i < 4; i++) {
            int id = tid + i * 256;
            int row = id >> 4, ch = id & 15;
            cpa16(vsb + (uint32_t)(row * 72 + ch * 4) * 4, gv + (size_t)row * Dc + ch * 4);
        }
        if (tid < 16)
            cpa16(smb + (uint32_t)(S_MS + s * 64 + tid * 4) * 4,
                  mask + (size_t)b * Sc + t * KT + tid * 4);
        CPA_COMMIT();
    };

    // ---- Q staging (own cp.async group)
    {
        const size_t rb = (size_t)(b * Sc + q0) * Dc + hoff;
#pragma unroll
        for (int i = 0; i < 16; i++) {
            int id = tid + i * 256;
            int row = id >> 5, ch = id & 31;
            const float* src = (ch < 16) ? (g_q + rb + (size_t)row * Dc + ch * 4)
                                         : (g_lq + rb + (size_t)row * Dc + (ch - 16) * 4);
            cpa16(smb + (uint32_t)(S_QS + row * 132 + ch * 4) * 4, src);
        }
        CPA_COMMIT();
    }
    issue_tile(0, 0);

    // ---- Q fragments -> registers (once). qa[kc][0..3] for dims kc*8.
    CPA_WAIT(1);            // Q group complete (tile0 may still be in flight)
    __syncthreads();
    uint32_t qa[16][4];
    {
        const uint32_t qlane = smb +
            ((uint32_t)(S_QS + (wid * 16 + (lane & 15)) * 132 + ((lane >> 4) << 2)) << 2);
#pragma unroll
        for (int kc = 0; kc < 16; kc++)
            ldsm4(qa[kc][0], qa[kc][1], qa[kc][2], qa[kc][3],
                  qlane + ((uint32_t)(kc * 8) << 2));
    }

    float m0 = -1e30f, m1 = -1e30f, l0 = 0.0f, l1 = 0.0f;
    float oacc[8][4];
#pragma unroll
    for (int nt = 0; nt < 8; nt++)
#pragma unroll
        for (int c = 0; c < 4; c++) oacc[nt][c] = 0.0f;

    const int srcA = (lane & ~3) | (tig >> 1);
    const int srcB = srcA + 2;
    const uint32_t k_lrow = ((uint32_t)(lane & 7) * 132 + ((lane >> 3) << 2)) << 2;

    for (int t = 0; t < Sc / KT; t++) {
        const int s = t & 1;
        if (t < Sc / KT - 1) issue_tile(t + 1, s ^ 1);
        if (t < Sc / KT - 1) { CPA_WAIT(1); } else { CPA_WAIT(0); }
        __syncthreads();

        const uint32_t ksl = smb + ((uint32_t)(S_KS + s * 8448) << 2) + k_lrow;
        const float* Vs = sm + S_VS + s * 4608;
        const float* ms = sm + S_MS + s * 64;

        // ---- QK: sacc[nt] = Q(16 rows) x K(64 keys), k-dim 128, via ldmatrix
        float sacc[8][4];
#pragma unroll
        for (int nt = 0; nt < 8; nt++)
#pragma unroll
            for (int c = 0; c < 4; c++) sacc[nt][c] = 0.0f;

#pragma unroll
        for (int kc2 = 0; kc2 < 8; kc2++) {
#pragma unroll
            for (int nt = 0; nt < 8; nt++) {
                uint32_t m0r, m1r, m2r, m3r;
                ldsm4(m0r, m1r, m2r, m3r,
                      ksl + ((uint32_t)(nt * 8 * 132 + kc2 * 16) << 2));
                uint32_t b01[2] = {m0r, m1r}, b23[2] = {m2r, m3r};
                mma8(sacc[nt], qa[2 * kc2],     b01);
                mma8(sacc[nt], qa[2 * kc2 + 1], b23);
            }
        }

        // ---- softmax (quad reductions)
        float mx0 = -1e30f, mx1 = -1e30f;
#pragma unroll
        for (int nt = 0; nt < 8; nt++) {
            const float mk0 = ms[nt * 8 + 2 * tig], mk1 = ms[nt * 8 + 2 * tig + 1];
            sacc[nt][0] = sacc[nt][0] * 0.125f + mk0;
            sacc[nt][1] = sacc[nt][1] * 0.125f + mk1;
            sacc[nt][2] = sacc[nt][2] * 0.125f + mk0;
            sacc[nt][3] = sacc[nt][3] * 0.125f + mk1;
            mx0 = fmaxf(mx0, fmaxf(sacc[nt][0], sacc[nt][1]));
            mx1 = fmaxf(mx1, fmaxf(sacc[nt][2], sacc[nt][3]));
        }
        mx0 = fmaxf(mx0, __shfl_xor_sync(0xffffffffu, mx0, 1));
        mx0 = fmaxf(mx0, __shfl_xor_sync(0xffffffffu, mx0, 2));
        mx1 = fmaxf(mx1, __shfl_xor_sync(0xffffffffu, mx1, 1));
        mx1 = fmaxf(mx1, __shfl_xor_sync(0xffffffffu, mx1, 2));

        const float mn0 = fmaxf(m0, mx0), mn1 = fmaxf(m1, mx1);
        const float al0 = __expf(m0 - mn0), al1 = __expf(m1 - mn1);
        float s0 = 0.0f, s1 = 0.0f;
#pragma unroll
        for (int nt = 0; nt < 8; nt++) {
            float p0 = __expf(sacc[nt][0] - mn0);
            float p1 = __expf(sacc[nt][1] - mn0);
            float p2 = __expf(sacc[nt][2] - mn1);
            float p3 = __expf(sacc[nt][3] - mn1);
            s0 += p0 + p1; s1 += p2 + p3;
            sacc[nt][0] = __uint_as_float(tf32r(p0));
            sacc[nt][1] = __uint_as_float(tf32r(p1));
            sacc[nt][2] = __uint_as_float(tf32r(p2));
            sacc[nt][3] = __uint_as_float(tf32r(p3));
        }
        s0 += __shfl_xor_sync(0xffffffffu, s0, 1);
        s0 += __shfl_xor_sync(0xffffffffu, s0, 2);
        s1 += __shfl_xor_sync(0xffffffffu, s1, 1);
        s1 += __shfl_xor_sync(0xffffffffu, s1, 2);
        l0 = l0 * al0 + s0;  l1 = l1 * al1 + s1;
        m0 = mn0;  m1 = mn1;

#pragma unroll
        for (int nt = 0; nt < 8; nt++) {
            oacc[nt][0] *= al0; oacc[nt][1] *= al0;
            oacc[nt][2] *= al1; oacc[nt][3] *= al1;
        }

        // ---- PV: O += P @ V  (P C-layout -> A-layout via quad shuffles)
#pragma unroll
        for (int kb = 0; kb < 8; kb++) {
            const float p0 = sacc[kb][0], p1 = sacc[kb][1];
            const float p2 = sacc[kb][2], p3 = sacc[kb][3];
            const float x0 = __shfl_sync(0xffffffffu, p0, srcA);
            const float x1 = __shfl_sync(0xffffffffu, p1, srcA);
            const float y0 = __shfl_sync(0xffffffffu, p2, srcA);
            const float y1 = __shfl_sync(0xffffffffu, p3, srcA);
            const float z0 = __shfl_sync(0xffffffffu, p0, srcB);
            const float z1 = __shfl_sync(0xffffffffu, p1, srcB);
            const float w0 = __shfl_sync(0xffffffffu, p2, srcB);
            const float w1 = __shfl_sync(0xffffffffu, p3, srcB);
            uint32_t aa[4];
            aa[0] = __float_as_uint((tig & 1) ? x1 : x0);
            aa[1] = __float_as_uint((tig & 1) ? y1 : y0);
            aa[2] = __float_as_uint((tig & 1) ? z1 : z0);
            aa[3] = __float_as_uint((tig & 1) ? w1 : w0);
#pragma unroll
            for (int nt = 0; nt < 8; nt++) {
                uint32_t bfr[2];
                bfr[0] = __float_as_uint(Vs[(kb * 8 + tig)     * 72 + nt * 8 + g]);
                bfr[1] = __float_as_uint(Vs[(kb * 8 + tig + 4) * 72 + nt * 8 + g]);
                mma8(oacc[nt], aa, bfr);
            }
        }
        __syncthreads();
    }

    // ---- epilogue
    const float i0 = 1.0f / l0, i1 = 1.0f / l1;
    const int row = b * Sc + q0 + wid * 16 + g;
    float* ob = out + (size_t)row * Dc + hoff;
#pragma unroll
    for (int nt = 0; nt < 8; nt++) {
        const int col = nt * 8 + 2 * tig;
        *(float2*)&ob[col] = make_float2(oacc[nt][0] * i0, oacc[nt][1] * i0);
        *(float2*)&ob[(size_t)8 * Dc + col] = make_float2(oacc[nt][2] * i1, oacc[nt][3] * i1);
    }
}

// ----------------------------------------------------------------------------
// Launch
// ----------------------------------------------------------------------------
extern "C" void kernel_launch(void* const* d_in, const int* in_sizes, int n_in,
                              void* d_out, int out_size)
{
    const float* hs   = (const float*)d_in[0];
    const float* lq   = (const float*)d_in[1];
    const float* lk   = (const float*)d_in[2];
    const float* mask = (const float*)d_in[3];
    const float* Wq   = (const float*)d_in[4];
    const float* bq   = (const float*)d_in[5];
    const float* Wk   = (const float*)d_in[6];
    const float* bk   = (const float*)d_in[7];
    const float* Wv   = (const float*)d_in[8];
    const float* bv   = (const float*)d_in[9];
    float* out = (float*)d_out;

    float *p_hs, *p_lq, *p_lk, *p_wq, *p_wk, *p_wv;
    cudaGetSymbolAddress((void**)&p_hs, g_hs);
    cudaGetSymbolAddress((void**)&p_lq, g_lq);
    cudaGetSymbolAddress((void**)&p_lk, g_lk);
    cudaGetSymbolAddress((void**)&p_wq, g_wq);
    cudaGetSymbolAddress((void**)&p_wk, g_wk);
    cudaGetSymbolAddress((void**)&p_wv, g_wv);

    const int nBig = (Mrows * Dc) / 4;
    const int nW   = (Dc * Dc) / 4;
    round_tf32<<<1024, 256>>>(hs, p_hs, nBig);
    round_tf32<<<1024, 256>>>(lq, p_lq, nBig);
    round_tf32<<<1024, 256>>>(lk, p_lk, nBig);
    round_tf32<<<256, 256>>>(Wq, p_wq, nW);
    round_tf32<<<256, 256>>>(Wk, p_wk, nW);
    round_tf32<<<256, 256>>>(Wv, p_wv, nW);

    cudaFuncSetAttribute(linear_tc, cudaFuncAttributeMaxDynamicSharedMemorySize, LIN_SMEM);
    dim3 gl(Dc / 128, Mrows / 128, 3);   // (6, 64, 3)
    linear_tc<<<gl, 256, LIN_SMEM>>>(bq, bk, bv);

    cudaFuncSetAttribute(attn_tc, cudaFuncAttributeMaxDynamicSharedMemorySize, ATT_SMEM);
    dim3 ga(Sc / 128, Hc, Bc);           // (16, 12, 4)
    attn_tc<<<ga, 256, ATT_SMEM>>>(mask, out);
}

// round 7
// speedup vs baseline: 1.0879x; 1.0003x over previous
#include <cuda_runtime.h>
#include <cstdint>

// ----------------------------------------------------------------------------
// Problem constants
// ----------------------------------------------------------------------------
#define Bc   4
#define Sc   2048
#define Dc   768
#define Hc   12
#define HDc  64
#define Mrows (Bc * Sc)   // 8192

// Scratch (device globals; all tf32-rounded)
__device__ float g_q [(size_t)Mrows * Dc];
__device__ float g_k [(size_t)Mrows * Dc];
__device__ float g_v [(size_t)Mrows * Dc];
__device__ float g_hs[(size_t)Mrows * Dc];
__device__ float g_lq[(size_t)Mrows * Dc];
__device__ float g_lk[(size_t)Mrows * Dc];
__device__ float g_wq[(size_t)Dc * Dc];
__device__ float g_wk[(size_t)Dc * Dc];
__device__ float g_wv[(size_t)Dc * Dc];

// ----------------------------------------------------------------------------
// Helpers
// ----------------------------------------------------------------------------
__device__ __forceinline__ uint32_t tf32r(float x) {
    uint32_t u;
    asm("cvt.rna.tf32.f32 %0, %1;" : "=r"(u) : "f"(x));
    return u;
}
__device__ __forceinline__ float ftf32(float x) { return __uint_as_float(tf32r(x)); }

__device__ __forceinline__ uint32_t smem_u32(const void* p) {
    uint32_t a;
    asm("{ .reg .u64 t; cvta.to.shared.u64 t, %1; cvt.u32.u64 %0, t; }" : "=r"(a) : "l"(p));
    return a;
}
__device__ __forceinline__ void cpa16(uint32_t dst, const void* src) {
    asm volatile("cp.async.cg.shared.global [%0], [%1], 16;" :: "r"(dst), "l"(src));
}
#define CPA_COMMIT() asm volatile("cp.async.commit_group;" ::: "memory")
#define CPA_WAIT(N)  asm volatile("cp.async.wait_group %0;" :: "n"(N) : "memory")

// ldmatrix x4 on 32-bit data: each 8x4-tf32 block distributes as [l/4][l%4]
__device__ __forceinline__ void ldsm4(uint32_t& r0, uint32_t& r1, uint32_t& r2, uint32_t& r3,
                                      uint32_t addr) {
    asm volatile("ldmatrix.sync.aligned.m8n8.x4.shared.b16 {%0,%1,%2,%3}, [%4];"
                 : "=r"(r0), "=r"(r1), "=r"(r2), "=r"(r3) : "r"(addr));
}

// d += a @ b  (m16n8k8, tf32 inputs, f32 accum)
__device__ __forceinline__ void mma8(float* d, const uint32_t* a, const uint32_t* b) {
    asm volatile(
        "mma.sync.aligned.m16n8k8.row.col.f32.tf32.tf32.f32 "
        "{%0,%1,%2,%3}, {%4,%5,%6,%7}, {%8,%9}, {%0,%1,%2,%3};\n"
        : "+f"(d[0]), "+f"(d[1]), "+f"(d[2]), "+f"(d[3])
        : "r"(a[0]), "r"(a[1]), "r"(a[2]), "r"(a[3]), "r"(b[0]), "r"(b[1]));
}

// ----------------------------------------------------------------------------
// Prep: tf32-round all six arrays in ONE launch (blockIdx.y selects array)
// ----------------------------------------------------------------------------
__global__ void round_all(const float* __restrict__ hs, const float* __restrict__ lq,
                          const float* __restrict__ lk, const float* __restrict__ wq,
                          const float* __restrict__ wk, const float* __restrict__ wv)
{
    const int which = blockIdx.y;
    const float* s;
    float* d;
    int n4;
    if (which == 0)      { s = hs; d = g_hs; n4 = (Mrows * Dc) / 4; }
    else if (which == 1) { s = lq; d = g_lq; n4 = (Mrows * Dc) / 4; }
    else if (which == 2) { s = lk; d = g_lk; n4 = (Mrows * Dc) / 4; }
    else if (which == 3) { s = wq; d = g_wq; n4 = (Dc * Dc) / 4; }
    else if (which == 4) { s = wk; d = g_wk; n4 = (Dc * Dc) / 4; }
    else                 { s = wv; d = g_wv; n4 = (Dc * Dc) / 4; }

    int i = blockIdx.x * blockDim.x + threadIdx.x;
    int stride = gridDim.x * blockDim.x;
    for (; i < n4; i += stride) {
        float4 v = ((const float4*)s)[i];
        v.x = ftf32(v.x); v.y = ftf32(v.y); v.z = ftf32(v.z); v.w = ftf32(v.w);
        ((float4*)d)[i] = v;
    }
}

// ----------------------------------------------------------------------------
// Linear: Y = X @ W^T + b  (tf32 mma.sync + ldmatrix, 128x128x32, cp.async x2)
// 8 warps (4x2), warp tile 32x64.  (unchanged from round 6 — verified)
// ----------------------------------------------------------------------------
#define LPAD 36
#define LIN_STAGE_F (128 * LPAD)
#define LIN_SMEM (4 * LIN_STAGE_F * (int)sizeof(float))   // 73728 B

__global__ __launch_bounds__(256, 2) void linear_tc(
    const float* __restrict__ bq,
    const float* __restrict__ bk,
    const float* __restrict__ bv)
{
    extern __shared__ __align__(16) float sm[];
    float* As[2] = { sm,               sm + 2 * LIN_STAGE_F };
    float* Bs[2] = { sm + LIN_STAGE_F, sm + 3 * LIN_STAGE_F };

    const int z = blockIdx.z;
    const float* X    = g_hs;
    const float* W    = (z == 0) ? g_wq : (z == 1) ? g_wk : g_wv;
    const float* bias = (z == 0) ? bq   : (z == 1) ? bk   : bv;
    float* Y          = (z == 0) ? g_q  : (z == 1) ? g_k  : g_v;

    const int tid = threadIdx.x;
    const int wid = tid >> 5, lane = tid & 31;
    const int g = lane >> 2, tig = lane & 3;
    const int warpm = wid >> 1, warpn = wid & 1;
    const int bm = blockIdx.y * 128, bn = blockIdx.x * 128;

    const int crow = tid >> 2, cch = (tid & 3) << 1;

    auto issue = [&](int it, int s) {
        const int k0 = it * 32;
        uint32_t ab = smem_u32(As[s]);
        uint32_t bb = smem_u32(Bs[s]);
#pragma unroll
        for (int rr = 0; rr < 2; rr++) {
            int row = crow + rr * 64;
#pragma unroll
            for (int cc = 0; cc < 2; cc++) {
                int ch = cch + cc;
                uint32_t off = (uint32_t)(row * LPAD + ch * 4) * 4;
                cpa16(ab + off, X + (size_t)(bm + row) * Dc + k0 + ch * 4);
                cpa16(bb + off, W + (size_t)(bn + row) * Dc + k0 + ch * 4);
            }
        }
        CPA_COMMIT();
    };

    float acc[2][8][4];
#pragma unroll
    for (int mt = 0; mt < 2; mt++)
#pragma unroll
        for (int nt = 0; nt < 8; nt++)
#pragma unroll
            for (int c = 0; c < 4; c++) acc[mt][nt][c] = 0.0f;

    const uint32_t a_lrow = (uint32_t)(warpm * 32 + (lane & 15)) * LPAD + ((lane >> 4) << 2);
    const uint32_t b_lrow = (uint32_t)(warpn * 64 + (lane & 7))  * LPAD + ((lane >> 3) << 2);

    issue(0, 0);
    for (int it = 0; it < 24; it++) {
        const int s = it & 1;
        if (it < 23) issue(it + 1, s ^ 1);
        if (it < 23) { CPA_WAIT(1); } else { CPA_WAIT(0); }
        __syncthreads();

        const uint32_t ab = smem_u32(As[s]) + (a_lrow << 2);
        const uint32_t bb = smem_u32(Bs[s]) + (b_lrow << 2);

#pragma unroll
        for (int kc2 = 0; kc2 < 2; kc2++) {
            uint32_t afr[2][2][4];
#pragma unroll
            for (int mt = 0; mt < 2; mt++)
#pragma unroll
                for (int kl = 0; kl < 2; kl++)
                    ldsm4(afr[mt][kl][0], afr[mt][kl][1], afr[mt][kl][2], afr[mt][kl][3],
                          ab + ((uint32_t)(mt * 16 * LPAD + (kc2 * 2 + kl) * 8) << 2));
#pragma unroll
            for (int nt = 0; nt < 8; nt++) {
                uint32_t m0, m1, m2, m3;
                ldsm4(m0, m1, m2, m3, bb + ((uint32_t)(nt * 8 * LPAD + kc2 * 16) << 2));
                uint32_t b01[2] = {m0, m1}, b23[2] = {m2, m3};
#pragma unroll
                for (int mt = 0; mt < 2; mt++) {
                    mma8(acc[mt][nt], afr[mt][0], b01);
                    mma8(acc[mt][nt], afr[mt][1], b23);
                }
            }
        }
        __syncthreads();
    }

#pragma unroll
    for (int mt = 0; mt < 2; mt++) {
        const int row0 = bm + warpm * 32 + mt * 16 + g;
#pragma unroll
        for (int nt = 0; nt < 8; nt++) {
            const int col = bn + warpn * 64 + nt * 8 + 2 * tig;
            const float bx = bias[col], by = bias[col + 1];
            *(float2*)&Y[(size_t)row0 * Dc + col] =
                make_float2(ftf32(acc[mt][nt][0] + bx), ftf32(acc[mt][nt][1] + by));
            *(float2*)&Y[(size_t)(row0 + 8) * Dc + col] =
                make_float2(ftf32(acc[mt][nt][2] + bx), ftf32(acc[mt][nt][3] + by));
        }
    }
}

// ----------------------------------------------------------------------------
// Flash attention (tf32 mma.sync), all-M, Q in regs, software-pipelined PV.
// Iteration t: QK(t) -> PV(t-1) -> softmax(t). 4-deep smem ring (race-free at
// warp skew 1 iter: write (t+2)%4 never hits reads t%4 or (t-1)%4).
// CTA = (b, h, 128-query tile), 256 threads = 8 warps x 16 q-rows.
// ----------------------------------------------------------------------------
#define KT 64
#define NT 32                        // Sc / KT
#define S_KS 0                       // 4 bufs x 8448 floats (64 x 132)
#define S_VS (4 * 8448)              // 33792, 4 bufs x 4608 floats (64 x 72)
#define S_MS (S_VS + 4 * 4608)       // 52224, 4 bufs x 64
#define ATT_F (S_MS + 256)           // 52480 floats
#define ATT_SMEM (ATT_F * (int)sizeof(float))   // 209920 B

__global__ __launch_bounds__(256, 1) void attn_tc(
    const float* __restrict__ mask,
    float* __restrict__ out)
{
    extern __shared__ __align__(16) float sm[];
    const uint32_t smb = smem_u32(sm);

    const int tid = threadIdx.x;
    const int wid = tid >> 5, lane = tid & 31;
    const int g = lane >> 2, tig = lane & 3;

    const int b = blockIdx.z, h = blockIdx.y, q0 = blockIdx.x * 128;
    const int hoff = h * HDc;

    auto issue_tile = [&](int t) {
        const int s = t & 3;
        const size_t rb = (size_t)(b * Sc + t * KT) * Dc + hoff;
        const float* gk  = g_k  + rb;
        const float* glk = g_lk + rb;
        const float* gv  = g_v  + rb;
        const uint32_t ksb = smb + (uint32_t)(S_KS + s * 8448) * 4;
        const uint32_t vsb = smb + (uint32_t)(S_VS + s * 4608) * 4;
#pragma unroll
        for (int i = 0; i < 8; i++) {
            int id = tid + i * 256;
            int row = id >> 5, ch = id & 31;
            const float* src = (ch < 16) ? (gk + (size_t)row * Dc + ch * 4)
                                         : (glk + (size_t)row * Dc + (ch - 16) * 4);
            cpa16(ksb + (uint32_t)(row * 132 + ch * 4) * 4, src);
        }
#pragma unroll
        for (int i = 0; i < 4; i++) {
            int id = tid + i * 256;
            int row = id >> 4, ch = id & 15;
            cpa16(vsb + (uint32_t)(row * 72 + ch * 4) * 4, gv + (size_t)row * Dc + ch * 4);
        }
        if (tid < 16)
            cpa16(smb + (uint32_t)(S_MS + s * 64 + tid * 4) * 4,
                  mask + (size_t)b * Sc + t * KT + tid * 4);
        CPA_COMMIT();
    };

    // ---- Q staging into KS bufs 0+1 (contiguous rows*132), then -> registers
    {
        const size_t rb = (size_t)(b * Sc + q0) * Dc + hoff;
#pragma unroll
        for (int i = 0; i < 16; i++) {
            int id = tid + i * 256;
            int row = id >> 5, ch = id & 31;
            const float* src = (ch < 16) ? (g_q + rb + (size_t)row * Dc + ch * 4)
                                         : (g_lq + rb + (size_t)row * Dc + (ch - 16) * 4);
            cpa16(smb + (uint32_t)(row * 132 + ch * 4) * 4, src);
        }
        CPA_COMMIT();
    }
    CPA_WAIT(0);
    __syncthreads();

    uint32_t qa[16][4];
    {
        const uint32_t qlane = smb +
            ((uint32_t)((wid * 16 + (lane & 15)) * 132 + ((lane >> 4) << 2)) << 2);
#pragma unroll
        for (int kc = 0; kc < 16; kc++)
            ldsm4(qa[kc][0], qa[kc][1], qa[kc][2], qa[kc][3],
                  qlane + ((uint32_t)(kc * 8) << 2));
    }
    __syncthreads();           // all warps done reading Q staging before tile 0 overwrites
    issue_tile(0);

    float m0 = -1e30f, m1 = -1e30f, l0 = 0.0f, l1 = 0.0f;
    float oacc[8][4];
    float pold[8][4];
#pragma unroll
    for (int nt = 0; nt < 8; nt++)
#pragma unroll
        for (int c = 0; c < 4; c++) { oacc[nt][c] = 0.0f; pold[nt][c] = 0.0f; }

    const int srcA = (lane & ~3) | (tig >> 1);
    const int srcB = srcA + 2;
    const uint32_t k_lrow = ((uint32_t)(lane & 7) * 132 + ((lane >> 3) << 2)) << 2;

    for (int t = 0; t < NT; t++) {
        if (t < NT - 1) { issue_tile(t + 1); CPA_WAIT(1); }
        else            { CPA_WAIT(0); }
        __syncthreads();

        const int s = t & 3, sp = (t - 1) & 3;
        const uint32_t ksl = smb + ((uint32_t)(S_KS + s * 8448) << 2) + k_lrow;
        const float* Vsp = sm + S_VS + sp * 4608;
        const float* ms  = sm + S_MS + s * 64;

        // ---- QK(t): sacc = Q(16 rows) x K(64 keys), k-dim 128
        float sacc[8][4];
#pragma unroll
        for (int nt = 0; nt < 8; nt++)
#pragma unroll
            for (int c = 0; c < 4; c++) sacc[nt][c] = 0.0f;

#pragma unroll
        for (int kc2 = 0; kc2 < 8; kc2++) {
#pragma unroll
            for (int nt = 0; nt < 8; nt++) {
                uint32_t m0r, m1r, m2r, m3r;
                ldsm4(m0r, m1r, m2r, m3r,
                      ksl + ((uint32_t)(nt * 8 * 132 + kc2 * 16) << 2));
                uint32_t b01[2] = {m0r, m1r}, b23[2] = {m2r, m3r};
                mma8(sacc[nt], qa[2 * kc2],     b01);
                mma8(sacc[nt], qa[2 * kc2 + 1], b23);
            }
        }

        // ---- PV(t-1): oacc += P_old @ V(t-1)  (overlaps softmax below)
        if (t > 0) {
#pragma unroll
            for (int kb = 0; kb < 8; kb++) {
                const float p0 = pold[kb][0], p1 = pold[kb][1];
                const float p2 = pold[kb][2], p3 = pold[kb][3];
                const float x0 = __shfl_sync(0xffffffffu, p0, srcA);
                const float x1 = __shfl_sync(0xffffffffu, p1, srcA);
                const float y0 = __shfl_sync(0xffffffffu, p2, srcA);
                const float y1 = __shfl_sync(0xffffffffu, p3, srcA);
                const float z0 = __shfl_sync(0xffffffffu, p0, srcB);
                const float z1 = __shfl_sync(0xffffffffu, p1, srcB);
                const float w0 = __shfl_sync(0xffffffffu, p2, srcB);
                const float w1 = __shfl_sync(0xffffffffu, p3, srcB);
                uint32_t aa[4];
                aa[0] = __float_as_uint((tig & 1) ? x1 : x0);
                aa[1] = __float_as_uint((tig & 1) ? y1 : y0);
                aa[2] = __float_as_uint((tig & 1) ? z1 : z0);
                aa[3] = __float_as_uint((tig & 1) ? w1 : w0);
#pragma unroll
                for (int nt = 0; nt < 8; nt++) {
                    uint32_t bfr[2];
                    bfr[0] = __float_as_uint(Vsp[(kb * 8 + tig)     * 72 + nt * 8 + g]);
                    bfr[1] = __float_as_uint(Vsp[(kb * 8 + tig + 4) * 72 + nt * 8 + g]);
                    mma8(oacc[nt], aa, bfr);
                }
            }
        }

        // ---- softmax(t): mask+scale, quad reductions, P -> pold, scale oacc
        float mx0 = -1e30f, mx1 = -1e30f;
#pragma unroll
        for (int nt = 0; nt < 8; nt++) {
            const float mk0 = ms[nt * 8 + 2 * tig], mk1 = ms[nt * 8 + 2 * tig + 1];
            sacc[nt][0] = sacc[nt][0] * 0.125f + mk0;
            sacc[nt][1] = sacc[nt][1] * 0.125f + mk1;
            sacc[nt][2] = sacc[nt][2] * 0.125f + mk0;
            sacc[nt][3] = sacc[nt][3] * 0.125f + mk1;
            mx0 = fmaxf(mx0, fmaxf(sacc[nt][0], sacc[nt][1]));
            mx1 = fmaxf(mx1, fmaxf(sacc[nt][2], sacc[nt][3]));
        }
        mx0 = fmaxf(mx0, __shfl_xor_sync(0xffffffffu, mx0, 1));
        mx0 = fmaxf(mx0, __shfl_xor_sync(0xffffffffu, mx0, 2));
        mx1 = fmaxf(mx1, __shfl_xor_sync(0xffffffffu, mx1, 1));
        mx1 = fmaxf(mx1, __shfl_xor_sync(0xffffffffu, mx1, 2));

        const float mn0 = fmaxf(m0, mx0), mn1 = fmaxf(m1, mx1);
        const float al0 = __expf(m0 - mn0), al1 = __expf(m1 - mn1);
        float s0 = 0.0f, s1 = 0.0f;
#pragma unroll
        for (int nt = 0; nt < 8; nt++) {
            float p0 = __expf(sacc[nt][0] - mn0);
            float p1 = __expf(sacc[nt][1] - mn0);
            float p2 = __expf(sacc[nt][2] - mn1);
            float p3 = __expf(sacc[nt][3] - mn1);
            s0 += p0 + p1; s1 += p2 + p3;
            pold[nt][0] = __uint_as_float(tf32r(p0));
            pold[nt][1] = __uint_as_float(tf32r(p1));
            pold[nt][2] = __uint_as_float(tf32r(p2));
            pold[nt][3] = __uint_as_float(tf32r(p3));
        }
        s0 += __shfl_xor_sync(0xffffffffu, s0, 1);
        s0 += __shfl_xor_sync(0xffffffffu, s0, 2);
        s1 += __shfl_xor_sync(0xffffffffu, s1, 1);
        s1 += __shfl_xor_sync(0xffffffffu, s1, 2);
        l0 = l0 * al0 + s0;  l1 = l1 * al1 + s1;
        m0 = mn0;  m1 = mn1;

        // scale AFTER the PV(t-1) accumulation above
#pragma unroll
        for (int nt = 0; nt < 8; nt++) {
            oacc[nt][0] *= al0; oacc[nt][1] *= al0;
            oacc[nt][2] *= al1; oacc[nt][3] *= al1;
        }
    }

    // ---- drain: PV(NT-1)
    {
        const float* Vsp = sm + S_VS + ((NT - 1) & 3) * 4608;
#pragma unroll
        for (int kb = 0; kb < 8; kb++) {
            const float p0 = pold[kb][0], p1 = pold[kb][1];
            const float p2 = pold[kb][2], p3 = pold[kb][3];
            const float x0 = __shfl_sync(0xffffffffu, p0, srcA);
            const float x1 = __shfl_sync(0xffffffffu, p1, srcA);
            const float y0 = __shfl_sync(0xffffffffu, p2, srcA);
            const float y1 = __shfl_sync(0xffffffffu, p3, srcA);
            const float z0 = __shfl_sync(0xffffffffu, p0, srcB);
            const float z1 = __shfl_sync(0xffffffffu, p1, srcB);
            const float w0 = __shfl_sync(0xffffffffu, p2, srcB);
            const float w1 = __shfl_sync(0xffffffffu, p3, srcB);
            uint32_t aa[4];
            aa[0] = __float_as_uint((tig & 1) ? x1 : x0);
            aa[1] = __float_as_uint((tig & 1) ? y1 : y0);
            aa[2] = __float_as_uint((tig & 1) ? z1 : z0);
            aa[3] = __float_as_uint((tig & 1) ? w1 : w0);
#pragma unroll
            for (int nt = 0; nt < 8; nt++) {
                uint32_t bfr[2];
                bfr[0] = __float_as_uint(Vsp[(kb * 8 + tig)     * 72 + nt * 8 + g]);
                bfr[1] = __float_as_uint(Vsp[(kb * 8 + tig + 4) * 72 + nt * 8 + g]);
                mma8(oacc[nt], aa, bfr);
            }
        }
    }

    // ---- epilogue
    const float i0 = 1.0f / l0, i1 = 1.0f / l1;
    const int row = b * Sc + q0 + wid * 16 + g;
    float* ob = out + (size_t)row * Dc + hoff;
#pragma unroll
    for (int nt = 0; nt < 8; nt++) {
        const int col = nt * 8 + 2 * tig;
        *(float2*)&ob[col] = make_float2(oacc[nt][0] * i0, oacc[nt][1] * i0);
        *(float2*)&ob[(size_t)8 * Dc + col] = make_float2(oacc[nt][2] * i1, oacc[nt][3] * i1);
    }
}

// ----------------------------------------------------------------------------
// Launch
// ----------------------------------------------------------------------------
extern "C" void kernel_launch(void* const* d_in, const int* in_sizes, int n_in,
                              void* d_out, int out_size)
{
    const float* hs   = (const float*)d_in[0];
    const float* lq   = (const float*)d_in[1];
    const float* lk   = (const float*)d_in[2];
    const float* mask = (const float*)d_in[3];
    const float* Wq   = (const float*)d_in[4];
    const float* bq   = (const float*)d_in[5];
    const float* Wk   = (const float*)d_in[6];
    const float* bk   = (const float*)d_in[7];
    const float* Wv   = (const float*)d_in[8];
    const float* bv   = (const float*)d_in[9];
    float* out = (float*)d_out;

    dim3 gp(512, 6);
    round_all<<<gp, 256>>>(hs, lq, lk, Wq, Wk, Wv);

    cudaFuncSetAttribute(linear_tc, cudaFuncAttributeMaxDynamicSharedMemorySize, LIN_SMEM);
    dim3 gl(Dc / 128, Mrows / 128, 3);   // (6, 64, 3)
    linear_tc<<<gl, 256, LIN_SMEM>>>(bq, bk, bv);

    cudaFuncSetAttribute(attn_tc, cudaFuncAttributeMaxDynamicSharedMemorySize, ATT_SMEM);
    dim3 ga(Sc / 128, Hc, Bc);           // (16, 12, 4)
    attn_tc<<<ga, 256, ATT_SMEM>>>(mask, out);
}

// round 8
// speedup vs baseline: 1.3468x; 1.2380x over previous
#include <cuda_runtime.h>
#include <cuda_fp16.h>
#include <cstdint>

// ----------------------------------------------------------------------------
// Problem constants
// ----------------------------------------------------------------------------
#define Bc   4
#define Sc   2048
#define Dc   768
#define Hc   12
#define HDc  64
#define Mrows (Bc * Sc)   // 8192

// Scratch (device globals; fp16)
__device__ __half g_q [(size_t)Mrows * Dc];
__device__ __half g_k [(size_t)Mrows * Dc];
__device__ __half g_v [(size_t)Mrows * Dc];
__device__ __half g_hs[(size_t)Mrows * Dc];
__device__ __half g_lq[(size_t)Mrows * Dc];
__device__ __half g_lk[(size_t)Mrows * Dc];
__device__ __half g_wq[(size_t)Dc * Dc];
__device__ __half g_wk[(size_t)Dc * Dc];
__device__ __half g_wv[(size_t)Dc * Dc];

// ----------------------------------------------------------------------------
// Helpers
// ----------------------------------------------------------------------------
__device__ __forceinline__ uint32_t smem_u32(const void* p) {
    uint32_t a;
    asm("{ .reg .u64 t; cvta.to.shared.u64 t, %1; cvt.u32.u64 %0, t; }" : "=r"(a) : "l"(p));
    return a;
}
__device__ __forceinline__ void cpa16(uint32_t dst, const void* src) {
    asm volatile("cp.async.cg.shared.global [%0], [%1], 16;" :: "r"(dst), "l"(src));
}
#define CPA_COMMIT() asm volatile("cp.async.commit_group;" ::: "memory")
#define CPA_WAIT(N)  asm volatile("cp.async.wait_group %0;" :: "n"(N) : "memory")

__device__ __forceinline__ void ldsm4(uint32_t& r0, uint32_t& r1, uint32_t& r2, uint32_t& r3,
                                      uint32_t addr) {
    asm volatile("ldmatrix.sync.aligned.m8n8.x4.shared.b16 {%0,%1,%2,%3}, [%4];"
                 : "=r"(r0), "=r"(r1), "=r"(r2), "=r"(r3) : "r"(addr));
}
__device__ __forceinline__ void ldsm4t(uint32_t& r0, uint32_t& r1, uint32_t& r2, uint32_t& r3,
                                       uint32_t addr) {
    asm volatile("ldmatrix.sync.aligned.m8n8.x4.trans.shared.b16 {%0,%1,%2,%3}, [%4];"
                 : "=r"(r0), "=r"(r1), "=r"(r2), "=r"(r3) : "r"(addr));
}

// d += a @ b  (m16n8k16, fp16 inputs, f32 accum)
__device__ __forceinline__ void mma16(float* d, const uint32_t* a, const uint32_t* b) {
    asm volatile(
        "mma.sync.aligned.m16n8k16.row.col.f32.f16.f16.f32 "
        "{%0,%1,%2,%3}, {%4,%5,%6,%7}, {%8,%9}, {%0,%1,%2,%3};\n"
        : "+f"(d[0]), "+f"(d[1]), "+f"(d[2]), "+f"(d[3])
        : "r"(a[0]), "r"(a[1]), "r"(a[2]), "r"(a[3]), "r"(b[0]), "r"(b[1]));
}

__device__ __forceinline__ uint32_t h2pack(float a, float b) {
    __half2 h = __floats2half2_rn(a, b);
    return *reinterpret_cast<uint32_t*>(&h);
}

// ----------------------------------------------------------------------------
// Prep: f32 -> fp16 for six arrays (blockIdx.y selects array)
// ----------------------------------------------------------------------------
__global__ void round_all(const float* __restrict__ hs, const float* __restrict__ lq,
                          const float* __restrict__ lk, const float* __restrict__ wq,
                          const float* __restrict__ wk, const float* __restrict__ wv)
{
    const int which = blockIdx.y;
    const float* s;
    __half* d;
    int n8;
    if (which == 0)      { s = hs; d = g_hs; n8 = (Mrows * Dc) / 8; }
    else if (which == 1) { s = lq; d = g_lq; n8 = (Mrows * Dc) / 8; }
    else if (which == 2) { s = lk; d = g_lk; n8 = (Mrows * Dc) / 8; }
    else if (which == 3) { s = wq; d = g_wq; n8 = (Dc * Dc) / 8; }
    else if (which == 4) { s = wk; d = g_wk; n8 = (Dc * Dc) / 8; }
    else                 { s = wv; d = g_wv; n8 = (Dc * Dc) / 8; }

    int i = blockIdx.x * blockDim.x + threadIdx.x;
    int stride = gridDim.x * blockDim.x;
    for (; i < n8; i += stride) {
        float4 v0 = ((const float4*)s)[2 * i];
        float4 v1 = ((const float4*)s)[2 * i + 1];
        uint4 o;
        o.x = h2pack(v0.x, v0.y);
        o.y = h2pack(v0.z, v0.w);
        o.z = h2pack(v1.x, v1.y);
        o.w = h2pack(v1.z, v1.w);
        ((uint4*)d)[i] = o;
    }
}

// ----------------------------------------------------------------------------
// Linear: Y = X @ W^T + b  (fp16 m16n8k16 + ldmatrix, 128x128x32, cp.async x2)
// 8 warps (4x2), warp tile 32x64. smem halfs, row stride 40.
// ----------------------------------------------------------------------------
#define LSTR 40
#define LIN_STAGE_H (128 * LSTR)                 // 5120 halfs / matrix / stage
#define LIN_SMEM (4 * LIN_STAGE_H * 2)           // 40960 B

__global__ __launch_bounds__(256, 2) void linear_tc(
    const float* __restrict__ bq,
    const float* __restrict__ bk,
    const float* __restrict__ bv)
{
    extern __shared__ __align__(16) __half smh[];
    const uint32_t smb = smem_u32(smh);

    const int z = blockIdx.z;
    const __half* X    = g_hs;
    const __half* W    = (z == 0) ? g_wq : (z == 1) ? g_wk : g_wv;
    const float* bias  = (z == 0) ? bq   : (z == 1) ? bk   : bv;
    __half* Y          = (z == 0) ? g_q  : (z == 1) ? g_k  : g_v;

    const int tid = threadIdx.x;
    const int wid = tid >> 5, lane = tid & 31;
    const int g = lane >> 2, tig = lane & 3;
    const int warpm = wid >> 1, warpn = wid & 1;
    const int bm = blockIdx.y * 128, bn = blockIdx.x * 128;

    // stage base (halfs): A[s] = s*2*LIN_STAGE_H, B[s] = that + LIN_STAGE_H
    auto issue = [&](int it, int s) {
        const int k0 = it * 32;
        const uint32_t ab = smb + (uint32_t)(s * 2 * LIN_STAGE_H) * 2;
        const uint32_t bb = ab + (uint32_t)LIN_STAGE_H * 2;
        // 128 rows x 4 chunks (16B = 8 halfs) per matrix; 512 chunks, 2/thread
#pragma unroll
        for (int i = 0; i < 2; i++) {
            int id = tid + i * 256;
            int row = id >> 2, ch = id & 3;
            uint32_t off = (uint32_t)(row * LSTR + ch * 8) * 2;
            cpa16(ab + off, X + (size_t)(bm + row) * Dc + k0 + ch * 8);
            cpa16(bb + off, W + (size_t)(bn + row) * Dc + k0 + ch * 8);
        }
        CPA_COMMIT();
    };

    float acc[2][8][4];
#pragma unroll
    for (int mt = 0; mt < 2; mt++)
#pragma unroll
        for (int nt = 0; nt < 8; nt++)
#pragma unroll
            for (int c = 0; c < 4; c++) acc[mt][nt][c] = 0.0f;

    const uint32_t a_loff = ((uint32_t)(warpm * 32 + (lane & 15)) * LSTR + ((lane >> 4) << 3)) * 2;
    const uint32_t b_loff = ((uint32_t)(warpn * 64 + (lane & 15)) * LSTR + ((lane >> 4) << 3)) * 2;

    issue(0, 0);
    for (int it = 0; it < 24; it++) {
        const int s = it & 1;
        if (it < 23) issue(it + 1, s ^ 1);
        if (it < 23) { CPA_WAIT(1); } else { CPA_WAIT(0); }
        __syncthreads();

        const uint32_t ab = smb + (uint32_t)(s * 2 * LIN_STAGE_H) * 2 + a_loff;
        const uint32_t bb = ab - a_loff + (uint32_t)LIN_STAGE_H * 2 + b_loff;

#pragma unroll
        for (int kc = 0; kc < 2; kc++) {       // two k16 chunks per 32-dim stage
            uint32_t afr[2][4];
#pragma unroll
            for (int mt = 0; mt < 2; mt++)
                ldsm4(afr[mt][0], afr[mt][1], afr[mt][2], afr[mt][3],
                      ab + ((uint32_t)(mt * 16 * LSTR + kc * 16) << 1));
#pragma unroll
            for (int ntp = 0; ntp < 4; ntp++) {
                uint32_t m0, m1, m2, m3;
                ldsm4(m0, m1, m2, m3, bb + ((uint32_t)(ntp * 16 * LSTR + kc * 16) << 1));
                uint32_t b0[2] = {m0, m2}, b1[2] = {m1, m3};
#pragma unroll
                for (int mt = 0; mt < 2; mt++) {
                    mma16(acc[mt][2 * ntp],     afr[mt], b0);
                    mma16(acc[mt][2 * ntp + 1], afr[mt], b1);
                }
            }
        }
        __syncthreads();
    }

    // Epilogue: bias (f32) + fp16 store
#pragma unroll
    for (int mt = 0; mt < 2; mt++) {
        const int row0 = bm + warpm * 32 + mt * 16 + g;
#pragma unroll
        for (int nt = 0; nt < 8; nt++) {
            const int col = bn + warpn * 64 + nt * 8 + 2 * tig;
            const float bx = bias[col], by = bias[col + 1];
            *(uint32_t*)&Y[(size_t)row0 * Dc + col] =
                h2pack(acc[mt][nt][0] + bx, acc[mt][nt][1] + by);
            *(uint32_t*)&Y[(size_t)(row0 + 8) * Dc + col] =
                h2pack(acc[mt][nt][2] + bx, acc[mt][nt][3] + by);
        }
    }
}

// ----------------------------------------------------------------------------
// Flash attention (fp16 m16n8k16), all-M, Q in regs, pipelined PV, occ 2.
// CTA = (b, h, 128-query tile), 256 threads = 8 warps x 16 q-rows.
// smem (halfs): KS 4 bufs x (64 x 136), VS 4 bufs x (64 x 72); MS f32 4 x 64.
// ----------------------------------------------------------------------------
#define KT 64
#define NT 32
#define KSTR 136
#define VSTR 72
#define KS_H 0                         // halfs; buf = 8704
#define VS_H (4 * 64 * KSTR)           // 34816; buf = 4608
#define MS_B ((VS_H + 4 * 64 * VSTR) * 2)   // byte offset 106496
#define ATT_SMEM (MS_B + 4 * 64 * 4)   // 107520 B

__global__ __launch_bounds__(256, 2) void attn_tc(
    const float* __restrict__ mask,
    float* __restrict__ out)
{
    extern __shared__ __align__(16) __half smh[];
    const uint32_t smb = smem_u32(smh);
    float* msf = (float*)((char*)smh + MS_B);

    const int tid = threadIdx.x;
    const int wid = tid >> 5, lane = tid & 31;
    const int g = lane >> 2, tig = lane & 3;

    const int b = blockIdx.z, h = blockIdx.y, q0 = blockIdx.x * 128;
    const int hoff = h * HDc;

    auto issue_tile = [&](int t) {
        const int s = t & 3;
        const size_t rb = (size_t)(b * Sc + t * KT) * Dc + hoff;
        const __half* gk  = g_k  + rb;
        const __half* glk = g_lk + rb;
        const __half* gv  = g_v  + rb;
        const uint32_t ksb = smb + (uint32_t)(KS_H + s * 64 * KSTR) * 2;
        const uint32_t vsb = smb + (uint32_t)(VS_H + s * 64 * VSTR) * 2;
        // KS: 64 rows x 16 chunks (8 halfs each): dims 0-63 k, 64-127 lk
#pragma unroll
        for (int i = 0; i < 4; i++) {
            int id = tid + i * 256;
            int row = id >> 4, ch = id & 15;
            const __half* src = (ch < 8) ? (gk + (size_t)row * Dc + ch * 8)
                                         : (glk + (size_t)row * Dc + (ch - 8) * 8);
            cpa16(ksb + (uint32_t)(row * KSTR + ch * 8) * 2, src);
        }
        // VS: 64 rows x 8 chunks
#pragma unroll
        for (int i = 0; i < 2; i++) {
            int id = tid + i * 256;
            int row = id >> 3, ch = id & 7;
            cpa16(vsb + (uint32_t)(row * VSTR + ch * 8) * 2, gv + (size_t)row * Dc + ch * 8);
        }
        if (tid < 16)
            cpa16(smb + (uint32_t)MS_B + (uint32_t)(s * 64 + tid * 4) * 4,
                  mask + (size_t)b * Sc + t * KT + tid * 4);
        CPA_COMMIT();
    };

    // ---- Q staging into KS bufs 0+1 (128 x 136 halfs), then -> registers
    {
        const size_t rb = (size_t)(b * Sc + q0) * Dc + hoff;
#pragma unroll
        for (int i = 0; i < 8; i++) {
            int id = tid + i * 256;
            int row = id >> 4, ch = id & 15;
            const __half* src = (ch < 8) ? (g_q + rb + (size_t)row * Dc + ch * 8)
                                         : (g_lq + rb + (size_t)row * Dc + (ch - 8) * 8);
            cpa16(smb + (uint32_t)(row * KSTR + ch * 8) * 2, src);
        }
        CPA_COMMIT();
    }
    CPA_WAIT(0);
    __syncthreads();

    uint32_t qa[8][4];     // A-frags: 8 k16 chunks over 128 dims
    {
        const uint32_t qlane = smb +
            ((uint32_t)((wid * 16 + (lane & 15)) * KSTR + ((lane >> 4) << 3)) << 1);
#pragma unroll
        for (int kc = 0; kc < 8; kc++)
            ldsm4(qa[kc][0], qa[kc][1], qa[kc][2], qa[kc][3],
                  qlane + ((uint32_t)(kc * 16) << 1));
    }
    __syncthreads();
    issue_tile(0);

    float m0 = -1e30f, m1 = -1e30f, l0 = 0.0f, l1 = 0.0f;
    float oacc[8][4];
    uint32_t pold[4][4];   // packed fp16 A-frags of P (4 k16 chunks x 4 regs)
#pragma unroll
    for (int nt = 0; nt < 8; nt++)
#pragma unroll
        for (int c = 0; c < 4; c++) oacc[nt][c] = 0.0f;
#pragma unroll
    for (int kb = 0; kb < 4; kb++)
#pragma unroll
        for (int c = 0; c < 4; c++) pold[kb][c] = 0u;

    const uint32_t k_loff = ((uint32_t)(lane & 15) * KSTR + ((lane >> 4) << 3)) << 1;
    const uint32_t v_loff = ((uint32_t)((lane & 7) + (((lane >> 3) & 1) << 3)) * VSTR
                             + ((lane >> 4) << 3)) << 1;

    for (int t = 0; t < NT; t++) {
        if (t < NT - 1) { issue_tile(t + 1); CPA_WAIT(1); }
        else            { CPA_WAIT(0); }
        __syncthreads();

        const int s = t & 3, sp = (t - 1) & 3;
        const uint32_t ksl = smb + ((uint32_t)(KS_H + s * 64 * KSTR) << 1) + k_loff;
        const uint32_t vsl = smb + ((uint32_t)(VS_H + sp * 64 * VSTR) << 1) + v_loff;
        const float* ms = msf + s * 64;

        // ---- QK(t): sacc = Q(16 rows) x K(64 keys), k-dim 128
        float sacc[8][4];
#pragma unroll
        for (int nt = 0; nt < 8; nt++)
#pragma unroll
            for (int c = 0; c < 4; c++) sacc[nt][c] = 0.0f;

#pragma unroll
        for (int kc = 0; kc < 8; kc++) {
#pragma unroll
            for (int nt2 = 0; nt2 < 4; nt2++) {
                uint32_t m0r, m1r, m2r, m3r;
                ldsm4(m0r, m1r, m2r, m3r,
                      ksl + ((uint32_t)(nt2 * 16 * KSTR + kc * 16) << 1));
                uint32_t b0[2] = {m0r, m2r}, b1[2] = {m1r, m3r};
                mma16(sacc[2 * nt2],     qa[kc], b0);
                mma16(sacc[2 * nt2 + 1], qa[kc], b1);
            }
        }

        // ---- PV(t-1): oacc += P_old @ V(t-1)  (independent of softmax below)
        if (t > 0) {
#pragma unroll
            for (int kb = 0; kb < 4; kb++) {
#pragma unroll
                for (int nt2 = 0; nt2 < 4; nt2++) {
                    uint32_t m0r, m1r, m2r, m3r;
                    ldsm4t(m0r, m1r, m2r, m3r,
                           vsl + ((uint32_t)(kb * 16 * VSTR + nt2 * 16) << 1));
                    uint32_t b0[2] = {m0r, m1r}, b1[2] = {m2r, m3r};
                    mma16(oacc[2 * nt2],     pold[kb], b0);
                    mma16(oacc[2 * nt2 + 1], pold[kb], b1);
                }
            }
        }

        // ---- softmax(t)
        float mx0 = -1e30f, mx1 = -1e30f;
#pragma unroll
        for (int nt = 0; nt < 8; nt++) {
            const float mk0 = ms[nt * 8 + 2 * tig], mk1 = ms[nt * 8 + 2 * tig + 1];
            sacc[nt][0] = sacc[nt][0] * 0.125f + mk0;
            sacc[nt][1] = sacc[nt][1] * 0.125f + mk1;
            sacc[nt][2] = sacc[nt][2] * 0.125f + mk0;
            sacc[nt][3] = sacc[nt][3] * 0.125f + mk1;
            mx0 = fmaxf(mx0, fmaxf(sacc[nt][0], sacc[nt][1]));
            mx1 = fmaxf(mx1, fmaxf(sacc[nt][2], sacc[nt][3]));
        }
        mx0 = fmaxf(mx0, __shfl_xor_sync(0xffffffffu, mx0, 1));
        mx0 = fmaxf(mx0, __shfl_xor_sync(0xffffffffu, mx0, 2));
        mx1 = fmaxf(mx1, __shfl_xor_sync(0xffffffffu, mx1, 1));
        mx1 = fmaxf(mx1, __shfl_xor_sync(0xffffffffu, mx1, 2));

        const float mn0 = fmaxf(m0, mx0), mn1 = fmaxf(m1, mx1);
        const float al0 = __expf(m0 - mn0), al1 = __expf(m1 - mn1);
        float s0 = 0.0f, s1 = 0.0f;
#pragma unroll
        for (int nt = 0; nt < 8; nt++) {
            sacc[nt][0] = __expf(sacc[nt][0] - mn0);
            sacc[nt][1] = __expf(sacc[nt][1] - mn0);
            sacc[nt][2] = __expf(sacc[nt][2] - mn1);
            sacc[nt][3] = __expf(sacc[nt][3] - mn1);
            s0 += sacc[nt][0] + sacc[nt][1];
            s1 += sacc[nt][2] + sacc[nt][3];
        }
        // pack P into fp16 A-frags (C-frag -> A-frag is a pure register pack)
#pragma unroll
        for (int kb = 0; kb < 4; kb++) {
            pold[kb][0] = h2pack(sacc[2 * kb][0],     sacc[2 * kb][1]);
            pold[kb][1] = h2pack(sacc[2 * kb][2],     sacc[2 * kb][3]);
            pold[kb][2] = h2pack(sacc[2 * kb + 1][0], sacc[2 * kb + 1][1]);
            pold[kb][3] = h2pack(sacc[2 * kb + 1][2], sacc[2 * kb + 1][3]);
        }
        s0 += __shfl_xor_sync(0xffffffffu, s0, 1);
        s0 += __shfl_xor_sync(0xffffffffu, s0, 2);
        s1 += __shfl_xor_sync(0xffffffffu, s1, 1);
        s1 += __shfl_xor_sync(0xffffffffu, s1, 2);
        l0 = l0 * al0 + s0;  l1 = l1 * al1 + s1;
        m0 = mn0;  m1 = mn1;

        // scale AFTER PV(t-1) accumulation
#pragma unroll
        for (int nt = 0; nt < 8; nt++) {
            oacc[nt][0] *= al0; oacc[nt][1] *= al0;
            oacc[nt][2] *= al1; oacc[nt][3] *= al1;
        }
    }

    // ---- drain: PV(NT-1)
    {
        const uint32_t vsl = smb + ((uint32_t)(VS_H + ((NT - 1) & 3) * 64 * VSTR) << 1) + v_loff;
#pragma unroll
        for (int kb = 0; kb < 4; kb++) {
#pragma unroll
            for (int nt2 = 0; nt2 < 4; nt2++) {
                uint32_t m0r, m1r, m2r, m3r;
                ldsm4t(m0r, m1r, m2r, m3r,
                       vsl + ((uint32_t)(kb * 16 * VSTR + nt2 * 16) << 1));
                uint32_t b0[2] = {m0r, m1r}, b1[2] = {m2r, m3r};
                mma16(oacc[2 * nt2],     pold[kb], b0);
                mma16(oacc[2 * nt2 + 1], pold[kb], b1);
            }
        }
    }

    // ---- epilogue (f32 out)
    const float i0 = 1.0f / l0, i1 = 1.0f / l1;
    const int row = b * Sc + q0 + wid * 16 + g;
    float* ob = out + (size_t)row * Dc + hoff;
#pragma unroll
    for (int nt = 0; nt < 8; nt++) {
        const int col = nt * 8 + 2 * tig;
        *(float2*)&ob[col] = make_float2(oacc[nt][0] * i0, oacc[nt][1] * i0);
        *(float2*)&ob[(size_t)8 * Dc + col] = make_float2(oacc[nt][2] * i1, oacc[nt][3] * i1);
    }
}

// ----------------------------------------------------------------------------
// Launch
// ----------------------------------------------------------------------------
extern "C" void kernel_launch(void* const* d_in, const int* in_sizes, int n_in,
                              void* d_out, int out_size)
{
    const float* hs   = (const float*)d_in[0];
    const float* lq   = (const float*)d_in[1];
    const float* lk   = (const float*)d_in[2];
    const float* mask = (const float*)d_in[3];
    const float* Wq   = (const float*)d_in[4];
    const float* bq   = (const float*)d_in[5];
    const float* Wk   = (const float*)d_in[6];
    const float* bk   = (const float*)d_in[7];
    const float* Wv   = (const float*)d_in[8];
    const float* bv   = (const float*)d_in[9];
    float* out = (float*)d_out;

    dim3 gp(512, 6);
    round_all<<<gp, 256>>>(hs, lq, lk, Wq, Wk, Wv);

    cudaFuncSetAttribute(linear_tc, cudaFuncAttributeMaxDynamicSharedMemorySize, LIN_SMEM);
    dim3 gl(Dc / 128, Mrows / 128, 3);   // (6, 64, 3)
    linear_tc<<<gl, 256, LIN_SMEM>>>(bq, bk, bv);

    cudaFuncSetAttribute(attn_tc, cudaFuncAttributeMaxDynamicSharedMemorySize, ATT_SMEM);
    dim3 ga(Sc / 128, Hc, Bc);           // (16, 12, 4)
    attn_tc<<<ga, 256, ATT_SMEM>>>(mask, out);
}

// round 9
// speedup vs baseline: 2.2081x; 1.6395x over previous
#include <cuda_runtime.h>
#include <cuda_fp16.h>
#include <cstdint>

// ----------------------------------------------------------------------------
// Problem constants
// ----------------------------------------------------------------------------
#define Bc   4
#define Sc   2048
#define Dc   768
#define Hc   12
#define HDc  64
#define Mrows (Bc * Sc)   // 8192

// Scratch (device globals)
__device__ __half g_q [(size_t)Mrows * Dc];
__device__ __half g_k [(size_t)Mrows * Dc];
__device__ __half g_v [(size_t)Mrows * Dc];
__device__ __half g_hs[(size_t)Mrows * Dc];
__device__ __half g_lq[(size_t)Mrows * Dc];
__device__ __half g_lk[(size_t)Mrows * Dc];
__device__ __half g_wq[(size_t)Dc * Dc];
__device__ __half g_wk[(size_t)Dc * Dc];
__device__ __half g_wv[(size_t)Dc * Dc];
__device__ float  g_mkl[(size_t)Bc * Sc];   // mask * log2(e)

// ----------------------------------------------------------------------------
// Helpers
// ----------------------------------------------------------------------------
__device__ __forceinline__ uint32_t smem_u32(const void* p) {
    uint32_t a;
    asm("{ .reg .u64 t; cvta.to.shared.u64 t, %1; cvt.u32.u64 %0, t; }" : "=r"(a) : "l"(p));
    return a;
}
__device__ __forceinline__ void cpa16(uint32_t dst, const void* src) {
    asm volatile("cp.async.cg.shared.global [%0], [%1], 16;" :: "r"(dst), "l"(src));
}
#define CPA_COMMIT() asm volatile("cp.async.commit_group;" ::: "memory")
#define CPA_WAIT(N)  asm volatile("cp.async.wait_group %0;" :: "n"(N) : "memory")

__device__ __forceinline__ void ldsm4(uint32_t& r0, uint32_t& r1, uint32_t& r2, uint32_t& r3,
                                      uint32_t addr) {
    asm volatile("ldmatrix.sync.aligned.m8n8.x4.shared.b16 {%0,%1,%2,%3}, [%4];"
                 : "=r"(r0), "=r"(r1), "=r"(r2), "=r"(r3) : "r"(addr));
}
__device__ __forceinline__ void ldsm4t(uint32_t& r0, uint32_t& r1, uint32_t& r2, uint32_t& r3,
                                       uint32_t addr) {
    asm volatile("ldmatrix.sync.aligned.m8n8.x4.trans.shared.b16 {%0,%1,%2,%3}, [%4];"
                 : "=r"(r0), "=r"(r1), "=r"(r2), "=r"(r3) : "r"(addr));
}

// d += a @ b  (m16n8k16, fp16 inputs, f32 accum)
__device__ __forceinline__ void mma16(float* d, const uint32_t* a, const uint32_t* b) {
    asm volatile(
        "mma.sync.aligned.m16n8k16.row.col.f32.f16.f16.f32 "
        "{%0,%1,%2,%3}, {%4,%5,%6,%7}, {%8,%9}, {%0,%1,%2,%3};\n"
        : "+f"(d[0]), "+f"(d[1]), "+f"(d[2]), "+f"(d[3])
        : "r"(a[0]), "r"(a[1]), "r"(a[2]), "r"(a[3]), "r"(b[0]), "r"(b[1]));
}

__device__ __forceinline__ uint32_t h2pack(float a, float b) {
    __half2 h = __floats2half2_rn(a, b);
    return *reinterpret_cast<uint32_t*>(&h);
}

// ----------------------------------------------------------------------------
// Prep: f32 -> fp16 for six arrays; mask -> f32 * log2(e)  (blockIdx.y selects)
// ----------------------------------------------------------------------------
__global__ void round_all(const float* __restrict__ hs, const float* __restrict__ lq,
                          const float* __restrict__ lk, const float* __restrict__ wq,
                          const float* __restrict__ wk, const float* __restrict__ wv,
                          const float* __restrict__ mask)
{
    const int which = blockIdx.y;
    int i = blockIdx.x * blockDim.x + threadIdx.x;
    int stride = gridDim.x * blockDim.x;

    if (which == 6) {   // mask prescale (tiny)
        const float L2E = 1.4426950408889634f;
        const int n4 = (Bc * Sc) / 4;
        for (; i < n4; i += stride) {
            float4 v = ((const float4*)mask)[i];
            v.x *= L2E; v.y *= L2E; v.z *= L2E; v.w *= L2E;
            ((float4*)g_mkl)[i] = v;
        }
        return;
    }

    const float* s;
    __half* d;
    int n8;
    if (which == 0)      { s = hs; d = g_hs; n8 = (Mrows * Dc) / 8; }
    else if (which == 1) { s = lq; d = g_lq; n8 = (Mrows * Dc) / 8; }
    else if (which == 2) { s = lk; d = g_lk; n8 = (Mrows * Dc) / 8; }
    else if (which == 3) { s = wq; d = g_wq; n8 = (Dc * Dc) / 8; }
    else if (which == 4) { s = wk; d = g_wk; n8 = (Dc * Dc) / 8; }
    else                 { s = wv; d = g_wv; n8 = (Dc * Dc) / 8; }

    for (; i < n8; i += stride) {
        float4 v0 = ((const float4*)s)[2 * i];
        float4 v1 = ((const float4*)s)[2 * i + 1];
        uint4 o;
        o.x = h2pack(v0.x, v0.y);
        o.y = h2pack(v0.z, v0.w);
        o.z = h2pack(v1.x, v1.y);
        o.w = h2pack(v1.z, v1.w);
        ((uint4*)d)[i] = o;
    }
}

// ----------------------------------------------------------------------------
// Linear: Y = X @ W^T + b  (fp16 m16n8k16 + ldmatrix, 128x128x32)
// 3-stage cp.async pipeline, ONE __syncthreads per k-iter.
// 8 warps (4x2), warp tile 32x64.
// ----------------------------------------------------------------------------
#define LSTR 40
#define LIN_STAGE_H (128 * LSTR)                 // 5120 halfs / matrix / stage
#define LIN_SMEM (6 * LIN_STAGE_H * 2)           // 61440 B (3 stages x 2 mats)

__global__ __launch_bounds__(256, 2) void linear_tc(
    const float* __restrict__ bq,
    const float* __restrict__ bk,
    const float* __restrict__ bv)
{
    extern __shared__ __align__(16) __half smh[];
    const uint32_t smb = smem_u32(smh);

    const int z = blockIdx.z;
    const __half* X    = g_hs;
    const __half* W    = (z == 0) ? g_wq : (z == 1) ? g_wk : g_wv;
    const float* bias  = (z == 0) ? bq   : (z == 1) ? bk   : bv;
    __half* Y          = (z == 0) ? g_q  : (z == 1) ? g_k  : g_v;

    const int tid = threadIdx.x;
    const int wid = tid >> 5, lane = tid & 31;
    const int g = lane >> 2, tig = lane & 3;
    const int warpm = wid >> 1, warpn = wid & 1;
    const int bm = blockIdx.y * 128, bn = blockIdx.x * 128;

    auto issue = [&](int it) {
        const int st = it % 3;
        const int k0 = it * 32;
        const uint32_t ab = smb + (uint32_t)(st * 2 * LIN_STAGE_H) * 2;
        const uint32_t bb = ab + (uint32_t)LIN_STAGE_H * 2;
#pragma unroll
        for (int i = 0; i < 2; i++) {
            int id = tid + i * 256;
            int row = id >> 2, ch = id & 3;
            uint32_t off = (uint32_t)(row * LSTR + ch * 8) * 2;
            cpa16(ab + off, X + (size_t)(bm + row) * Dc + k0 + ch * 8);
            cpa16(bb + off, W + (size_t)(bn + row) * Dc + k0 + ch * 8);
        }
        CPA_COMMIT();
    };

    float acc[2][8][4];
#pragma unroll
    for (int mt = 0; mt < 2; mt++)
#pragma unroll
        for (int nt = 0; nt < 8; nt++)
#pragma unroll
            for (int c = 0; c < 4; c++) acc[mt][nt][c] = 0.0f;

    const uint32_t a_loff = ((uint32_t)(warpm * 32 + (lane & 15)) * LSTR + ((lane >> 4) << 3)) * 2;
    const uint32_t b_loff = ((uint32_t)(warpn * 64 + (lane & 15)) * LSTR + ((lane >> 4) << 3)) * 2;

    issue(0);
    issue(1);
    for (int it = 0; it < 24; it++) {
        if (it == 23) { CPA_WAIT(0); } else { CPA_WAIT(1); }
        __syncthreads();
        if (it < 22) issue(it + 2);

        const int st = it % 3;
        const uint32_t ab = smb + (uint32_t)(st * 2 * LIN_STAGE_H) * 2 + a_loff;
        const uint32_t bb = smb + (uint32_t)(st * 2 * LIN_STAGE_H + LIN_STAGE_H) * 2 + b_loff;

#pragma unroll
        for (int kc = 0; kc < 2; kc++) {
            uint32_t afr[2][4];
#pragma unroll
            for (int mt = 0; mt < 2; mt++)
                ldsm4(afr[mt][0], afr[mt][1], afr[mt][2], afr[mt][3],
                      ab + ((uint32_t)(mt * 16 * LSTR + kc * 16) << 1));
#pragma unroll
            for (int ntp = 0; ntp < 4; ntp++) {
                uint32_t m0, m1, m2, m3;
                ldsm4(m0, m1, m2, m3, bb + ((uint32_t)(ntp * 16 * LSTR + kc * 16) << 1));
                uint32_t b0[2] = {m0, m2}, b1[2] = {m1, m3};
#pragma unroll
                for (int mt = 0; mt < 2; mt++) {
                    mma16(acc[mt][2 * ntp],     afr[mt], b0);
                    mma16(acc[mt][2 * ntp + 1], afr[mt], b1);
                }
            }
        }
    }

    // Epilogue: bias (f32) + fp16 store
#pragma unroll
    for (int mt = 0; mt < 2; mt++) {
        const int row0 = bm + warpm * 32 + mt * 16 + g;
#pragma unroll
        for (int nt = 0; nt < 8; nt++) {
            const int col = bn + warpn * 64 + nt * 8 + 2 * tig;
            const float bx = bias[col], by = bias[col + 1];
            *(uint32_t*)&Y[(size_t)row0 * Dc + col] =
                h2pack(acc[mt][nt][0] + bx, acc[mt][nt][1] + by);
            *(uint32_t*)&Y[(size_t)(row0 + 8) * Dc + col] =
                h2pack(acc[mt][nt][2] + bx, acc[mt][nt][3] + by);
        }
    }
}

// ----------------------------------------------------------------------------
// Flash attention (fp16 m16n8k16), all-M, Q in regs, pipelined PV, exp2 softmax.
// CTA = (b, h, 128-query tile), 256 threads = 8 warps x 16 q-rows.
// ----------------------------------------------------------------------------
#define KT 64
#define NT 32
#define KSTR 136
#define VSTR 72
#define KS_H 0
#define VS_H (4 * 64 * KSTR)
#define MS_B ((VS_H + 4 * 64 * VSTR) * 2)
#define ATT_SMEM (MS_B + 4 * 64 * 4)   // 107520 B

__global__ __launch_bounds__(256, 2) void attn_tc(
    float* __restrict__ out)
{
    extern __shared__ __align__(16) __half smh[];
    const uint32_t smb = smem_u32(smh);
    float* msf = (float*)((char*)smh + MS_B);

    const int tid = threadIdx.x;
    const int wid = tid >> 5, lane = tid & 31;
    const int g = lane >> 2, tig = lane & 3;

    const int b = blockIdx.z, h = blockIdx.y, q0 = blockIdx.x * 128;
    const int hoff = h * HDc;

    auto issue_tile = [&](int t) {
        const int s = t & 3;
        const size_t rb = (size_t)(b * Sc + t * KT) * Dc + hoff;
        const __half* gk  = g_k  + rb;
        const __half* glk = g_lk + rb;
        const __half* gv  = g_v  + rb;
        const uint32_t ksb = smb + (uint32_t)(KS_H + s * 64 * KSTR) * 2;
        const uint32_t vsb = smb + (uint32_t)(VS_H + s * 64 * VSTR) * 2;
#pragma unroll
        for (int i = 0; i < 4; i++) {
            int id = tid + i * 256;
            int row = id >> 4, ch = id & 15;
            const __half* src = (ch < 8) ? (gk + (size_t)row * Dc + ch * 8)
                                         : (glk + (size_t)row * Dc + (ch - 8) * 8);
            cpa16(ksb + (uint32_t)(row * KSTR + ch * 8) * 2, src);
        }
#pragma unroll
        for (int i = 0; i < 2; i++) {
            int id = tid + i * 256;
            int row = id >> 3, ch = id & 7;
            cpa16(vsb + (uint32_t)(row * VSTR + ch * 8) * 2, gv + (size_t)row * Dc + ch * 8);
        }
        if (tid < 16)
            cpa16(smb + (uint32_t)MS_B + (uint32_t)(s * 64 + tid * 4) * 4,
                  g_mkl + (size_t)b * Sc + t * KT + tid * 4);
        CPA_COMMIT();
    };

    // ---- Q staging into KS bufs 0+1, then -> registers
    {
        const size_t rb = (size_t)(b * Sc + q0) * Dc + hoff;
#pragma unroll
        for (int i = 0; i < 8; i++) {
            int id = tid + i * 256;
            int row = id >> 4, ch = id & 15;
            const __half* src = (ch < 8) ? (g_q + rb + (size_t)row * Dc + ch * 8)
                                         : (g_lq + rb + (size_t)row * Dc + (ch - 8) * 8);
            cpa16(smb + (uint32_t)(row * KSTR + ch * 8) * 2, src);
        }
        CPA_COMMIT();
    }
    CPA_WAIT(0);
    __syncthreads();

    uint32_t qa[8][4];
    {
        const uint32_t qlane = smb +
            ((uint32_t)((wid * 16 + (lane & 15)) * KSTR + ((lane >> 4) << 3)) << 1);
#pragma unroll
        for (int kc = 0; kc < 8; kc++)
            ldsm4(qa[kc][0], qa[kc][1], qa[kc][2], qa[kc][3],
                  qlane + ((uint32_t)(kc * 16) << 1));
    }
    __syncthreads();
    issue_tile(0);

    float m0 = -1e30f, m1 = -1e30f, l0 = 0.0f, l1 = 0.0f;
    float oacc[8][4];
    uint32_t pold[4][4];
#pragma unroll
    for (int nt = 0; nt < 8; nt++)
#pragma unroll
        for (int c = 0; c < 4; c++) oacc[nt][c] = 0.0f;
#pragma unroll
    for (int kb = 0; kb < 4; kb++)
#pragma unroll
        for (int c = 0; c < 4; c++) pold[kb][c] = 0u;

    const uint32_t k_loff = ((uint32_t)(lane & 15) * KSTR + ((lane >> 4) << 3)) << 1;
    const uint32_t v_loff = ((uint32_t)((lane & 7) + (((lane >> 3) & 1) << 3)) * VSTR
                             + ((lane >> 4) << 3)) << 1;
    const float C1 = 0.18033688011112042f;   // 0.125 * log2(e)

    for (int t = 0; t < NT; t++) {
        if (t < NT - 1) { issue_tile(t + 1); CPA_WAIT(1); }
        else            { CPA_WAIT(0); }
        __syncthreads();

        const int s = t & 3, sp = (t - 1) & 3;
        const uint32_t ksl = smb + ((uint32_t)(KS_H + s * 64 * KSTR) << 1) + k_loff;
        const uint32_t vsl = smb + ((uint32_t)(VS_H + sp * 64 * VSTR) << 1) + v_loff;
        const float* ms = msf + s * 64;

        // ---- QK(t)
        float sacc[8][4];
#pragma unroll
        for (int nt = 0; nt < 8; nt++)
#pragma unroll
            for (int c = 0; c < 4; c++) sacc[nt][c] = 0.0f;

#pragma unroll
        for (int kc = 0; kc < 8; kc++) {
#pragma unroll
            for (int nt2 = 0; nt2 < 4; nt2++) {
                uint32_t m0r, m1r, m2r, m3r;
                ldsm4(m0r, m1r, m2r, m3r,
                      ksl + ((uint32_t)(nt2 * 16 * KSTR + kc * 16) << 1));
                uint32_t b0[2] = {m0r, m2r}, b1[2] = {m1r, m3r};
                mma16(sacc[2 * nt2],     qa[kc], b0);
                mma16(sacc[2 * nt2 + 1], qa[kc], b1);
            }
        }

        // ---- PV(t-1)
        if (t > 0) {
#pragma unroll
            for (int kb = 0; kb < 4; kb++) {
#pragma unroll
                for (int nt2 = 0; nt2 < 4; nt2++) {
                    uint32_t m0r, m1r, m2r, m3r;
                    ldsm4t(m0r, m1r, m2r, m3r,
                           vsl + ((uint32_t)(kb * 16 * VSTR + nt2 * 16) << 1));
                    uint32_t b0[2] = {m0r, m1r}, b1[2] = {m2r, m3r};
                    mma16(oacc[2 * nt2],     pold[kb], b0);
                    mma16(oacc[2 * nt2 + 1], pold[kb], b1);
                }
            }
        }

        // ---- softmax(t) in log2 domain
        float mx0 = -1e30f, mx1 = -1e30f;
#pragma unroll
        for (int nt = 0; nt < 8; nt++) {
            const float mk0 = ms[nt * 8 + 2 * tig], mk1 = ms[nt * 8 + 2 * tig + 1];
            sacc[nt][0] = sacc[nt][0] * C1 + mk0;
            sacc[nt][1] = sacc[nt][1] * C1 + mk1;
            sacc[nt][2] = sacc[nt][2] * C1 + mk0;
            sacc[nt][3] = sacc[nt][3] * C1 + mk1;
            mx0 = fmaxf(mx0, fmaxf(sacc[nt][0], sacc[nt][1]));
            mx1 = fmaxf(mx1, fmaxf(sacc[nt][2], sacc[nt][3]));
        }
        mx0 = fmaxf(mx0, __shfl_xor_sync(0xffffffffu, mx0, 1));
        mx0 = fmaxf(mx0, __shfl_xor_sync(0xffffffffu, mx0, 2));
        mx1 = fmaxf(mx1, __shfl_xor_sync(0xffffffffu, mx1, 1));
        mx1 = fmaxf(mx1, __shfl_xor_sync(0xffffffffu, mx1, 2));

        const float mn0 = fmaxf(m0, mx0), mn1 = fmaxf(m1, mx1);
        const float al0 = exp2f(m0 - mn0), al1 = exp2f(m1 - mn1);
        float s0 = 0.0f, s1 = 0.0f;
#pragma unroll
        for (int nt = 0; nt < 8; nt++) {
            sacc[nt][0] = exp2f(sacc[nt][0] - mn0);
            sacc[nt][1] = exp2f(sacc[nt][1] - mn0);
            sacc[nt][2] = exp2f(sacc[nt][2] - mn1);
            sacc[nt][3] = exp2f(sacc[nt][3] - mn1);
            s0 += sacc[nt][0] + sacc[nt][1];
            s1 += sacc[nt][2] + sacc[nt][3];
        }
#pragma unroll
        for (int kb = 0; kb < 4; kb++) {
            pold[kb][0] = h2pack(sacc[2 * kb][0],     sacc[2 * kb][1]);
            pold[kb][1] = h2pack(sacc[2 * kb][2],     sacc[2 * kb][3]);
            pold[kb][2] = h2pack(sacc[2 * kb + 1][0], sacc[2 * kb + 1][1]);
            pold[kb][3] = h2pack(sacc[2 * kb + 1][2], sacc[2 * kb + 1][3]);
        }
        s0 += __shfl_xor_sync(0xffffffffu, s0, 1);
        s0 += __shfl_xor_sync(0xffffffffu, s0, 2);
        s1 += __shfl_xor_sync(0xffffffffu, s1, 1);
        s1 += __shfl_xor_sync(0xffffffffu, s1, 2);
        l0 = l0 * al0 + s0;  l1 = l1 * al1 + s1;
        m0 = mn0;  m1 = mn1;

        // scale oacc only when some row's max actually moved (warp-uniform)
        const bool noscale = __all_sync(0xffffffffu, (al0 == 1.0f) & (al1 == 1.0f));
        if (!noscale) {
#pragma unroll
            for (int nt = 0; nt < 8; nt++) {
                oacc[nt][0] *= al0; oacc[nt][1] *= al0;
                oacc[nt][2] *= al1; oacc[nt][3] *= al1;
            }
        }
    }

    // ---- drain: PV(NT-1)
    {
        const uint32_t vsl = smb + ((uint32_t)(VS_H + ((NT - 1) & 3) * 64 * VSTR) << 1) + v_loff;
#pragma unroll
        for (int kb = 0; kb < 4; kb++) {
#pragma unroll
            for (int nt2 = 0; nt2 < 4; nt2++) {
                uint32_t m0r, m1r, m2r, m3r;
                ldsm4t(m0r, m1r, m2r, m3r,
                       vsl + ((uint32_t)(kb * 16 * VSTR + nt2 * 16) << 1));
                uint32_t b0[2] = {m0r, m1r}, b1[2] = {m2r, m3r};
                mma16(oacc[2 * nt2],     pold[kb], b0);
                mma16(oacc[2 * nt2 + 1], pold[kb], b1);
            }
        }
    }

    // ---- epilogue (f32 out)
    const float i0 = 1.0f / l0, i1 = 1.0f / l1;
    const int row = b * Sc + q0 + wid * 16 + g;
    float* ob = out + (size_t)row * Dc + hoff;
#pragma unroll
    for (int nt = 0; nt < 8; nt++) {
        const int col = nt * 8 + 2 * tig;
        *(float2*)&ob[col] = make_float2(oacc[nt][0] * i0, oacc[nt][1] * i0);
        *(float2*)&ob[(size_t)8 * Dc + col] = make_float2(oacc[nt][2] * i1, oacc[nt][3] * i1);
    }
}

// ----------------------------------------------------------------------------
// Launch
// ----------------------------------------------------------------------------
extern "C" void kernel_launch(void* const* d_in, const int* in_sizes, int n_in,
                              void* d_out, int out_size)
{
    const float* hs   = (const float*)d_in[0];
    const float* lq   = (const float*)d_in[1];
    const float* lk   = (const float*)d_in[2];
    const float* mask = (const float*)d_in[3];
    const float* Wq   = (const float*)d_in[4];
    const float* bq   = (const float*)d_in[5];
    const float* Wk   = (const float*)d_in[6];
    const float* bk   = (const float*)d_in[7];
    const float* Wv   = (const float*)d_in[8];
    const float* bv   = (const float*)d_in[9];
    float* out = (float*)d_out;

    dim3 gp(512, 7);
    round_all<<<gp, 256>>>(hs, lq, lk, Wq, Wk, Wv, mask);

    cudaFuncSetAttribute(linear_tc, cudaFuncAttributeMaxDynamicSharedMemorySize, LIN_SMEM);
    dim3 gl(Dc / 128, Mrows / 128, 3);   // (6, 64, 3)
    linear_tc<<<gl, 256, LIN_SMEM>>>(bq, bk, bv);

    cudaFuncSetAttribute(attn_tc, cudaFuncAttributeMaxDynamicSharedMemorySize, ATT_SMEM);
    dim3 ga(Sc / 128, Hc, Bc);           // (16, 12, 4)
    attn_tc<<<ga, 256, ATT_SMEM>>>(out);
}

// round 10
// speedup vs baseline: 2.3590x; 1.0683x over previous
#include <cuda_runtime.h>
#include <cuda_fp16.h>
#include <cstdint>

// ----------------------------------------------------------------------------
// Problem constants
// ----------------------------------------------------------------------------
#define Bc   4
#define Sc   2048
#define Dc   768
#define Hc   12
#define HDc  64
#define Mrows (Bc * Sc)   // 8192

// Scratch (device globals)
__device__ __half g_q [(size_t)Mrows * Dc];
__device__ __half g_k [(size_t)Mrows * Dc];
__device__ __half g_v [(size_t)Mrows * Dc];
__device__ __half g_hs[(size_t)Mrows * Dc];
__device__ __half g_lq[(size_t)Mrows * Dc];
__device__ __half g_lk[(size_t)Mrows * Dc];
__device__ __half g_wq[(size_t)Dc * Dc];
__device__ __half g_wk[(size_t)Dc * Dc];
__device__ __half g_wv[(size_t)Dc * Dc];
__device__ float  g_mkl[(size_t)Bc * Sc];   // mask * log2(e) - 8

// ----------------------------------------------------------------------------
// Helpers
// ----------------------------------------------------------------------------
__device__ __forceinline__ uint32_t smem_u32(const void* p) {
    uint32_t a;
    asm("{ .reg .u64 t; cvta.to.shared.u64 t, %1; cvt.u32.u64 %0, t; }" : "=r"(a) : "l"(p));
    return a;
}
__device__ __forceinline__ void cpa16(uint32_t dst, const void* src) {
    asm volatile("cp.async.cg.shared.global [%0], [%1], 16;" :: "r"(dst), "l"(src));
}
#define CPA_COMMIT() asm volatile("cp.async.commit_group;" ::: "memory")
#define CPA_WAIT(N)  asm volatile("cp.async.wait_group %0;" :: "n"(N) : "memory")

__device__ __forceinline__ void ldsm4(uint32_t& r0, uint32_t& r1, uint32_t& r2, uint32_t& r3,
                                      uint32_t addr) {
    asm volatile("ldmatrix.sync.aligned.m8n8.x4.shared.b16 {%0,%1,%2,%3}, [%4];"
                 : "=r"(r0), "=r"(r1), "=r"(r2), "=r"(r3) : "r"(addr));
}
__device__ __forceinline__ void ldsm4t(uint32_t& r0, uint32_t& r1, uint32_t& r2, uint32_t& r3,
                                       uint32_t addr) {
    asm volatile("ldmatrix.sync.aligned.m8n8.x4.trans.shared.b16 {%0,%1,%2,%3}, [%4];"
                 : "=r"(r0), "=r"(r1), "=r"(r2), "=r"(r3) : "r"(addr));
}
__device__ __forceinline__ void ldsm2t(uint32_t& r0, uint32_t& r1, uint32_t addr) {
    asm volatile("ldmatrix.sync.aligned.m8n8.x2.trans.shared.b16 {%0,%1}, [%2];"
                 : "=r"(r0), "=r"(r1) : "r"(addr));
}

// d += a @ b  (m16n8k16, fp16 inputs, f32 accum)
__device__ __forceinline__ void mma16(float* d, const uint32_t* a, const uint32_t* b) {
    asm volatile(
        "mma.sync.aligned.m16n8k16.row.col.f32.f16.f16.f32 "
        "{%0,%1,%2,%3}, {%4,%5,%6,%7}, {%8,%9}, {%0,%1,%2,%3};\n"
        : "+f"(d[0]), "+f"(d[1]), "+f"(d[2]), "+f"(d[3])
        : "r"(a[0]), "r"(a[1]), "r"(a[2]), "r"(a[3]), "r"(b[0]), "r"(b[1]));
}

__device__ __forceinline__ uint32_t h2pack(float a, float b) {
    __half2 h = __floats2half2_rn(a, b);
    return *reinterpret_cast<uint32_t*>(&h);
}

// ----------------------------------------------------------------------------
// Prep: f32 -> fp16 for six arrays; mask -> mask*log2(e) - 8  (blockIdx.y sel)
// ----------------------------------------------------------------------------
__global__ void round_all(const float* __restrict__ hs, const float* __restrict__ lq,
                          const float* __restrict__ lk, const float* __restrict__ wq,
                          const float* __restrict__ wk, const float* __restrict__ wv,
                          const float* __restrict__ mask)
{
    const int which = blockIdx.y;
    int i = blockIdx.x * blockDim.x + threadIdx.x;
    int stride = gridDim.x * blockDim.x;

    if (which == 6) {
        const float L2E = 1.4426950408889634f;
        const int n4 = (Bc * Sc) / 4;
        for (; i < n4; i += stride) {
            float4 v = ((const float4*)mask)[i];
            v.x = v.x * L2E - 8.0f; v.y = v.y * L2E - 8.0f;
            v.z = v.z * L2E - 8.0f; v.w = v.w * L2E - 8.0f;
            ((float4*)g_mkl)[i] = v;
        }
        return;
    }

    const float* s;
    __half* d;
    int n8;
    if (which == 0)      { s = hs; d = g_hs; n8 = (Mrows * Dc) / 8; }
    else if (which == 1) { s = lq; d = g_lq; n8 = (Mrows * Dc) / 8; }
    else if (which == 2) { s = lk; d = g_lk; n8 = (Mrows * Dc) / 8; }
    else if (which == 3) { s = wq; d = g_wq; n8 = (Dc * Dc) / 8; }
    else if (which == 4) { s = wk; d = g_wk; n8 = (Dc * Dc) / 8; }
    else                 { s = wv; d = g_wv; n8 = (Dc * Dc) / 8; }

    for (; i < n8; i += stride) {
        float4 v0 = ((const float4*)s)[2 * i];
        float4 v1 = ((const float4*)s)[2 * i + 1];
        uint4 o;
        o.x = h2pack(v0.x, v0.y);
        o.y = h2pack(v0.z, v0.w);
        o.z = h2pack(v1.x, v1.y);
        o.w = h2pack(v1.z, v1.w);
        ((uint4*)d)[i] = o;
    }
}

// ----------------------------------------------------------------------------
// Linear: Y = X @ W^T + b  (fp16 m16n8k16 + ldmatrix, 128x128x32)
// 3-stage cp.async pipeline, one __syncthreads per k-iter. (verified R9)
// ----------------------------------------------------------------------------
#define LSTR 40
#define LIN_STAGE_H (128 * LSTR)
#define LIN_SMEM (6 * LIN_STAGE_H * 2)           // 61440 B

__global__ __launch_bounds__(256, 2) void linear_tc(
    const float* __restrict__ bq,
    const float* __restrict__ bk,
    const float* __restrict__ bv)
{
    extern __shared__ __align__(16) __half smh[];
    const uint32_t smb = smem_u32(smh);

    const int z = blockIdx.z;
    const __half* X    = g_hs;
    const __half* W    = (z == 0) ? g_wq : (z == 1) ? g_wk : g_wv;
    const float* bias  = (z == 0) ? bq   : (z == 1) ? bk   : bv;
    __half* Y          = (z == 0) ? g_q  : (z == 1) ? g_k  : g_v;

    const int tid = threadIdx.x;
    const int wid = tid >> 5, lane = tid & 31;
    const int g = lane >> 2, tig = lane & 3;
    const int warpm = wid >> 1, warpn = wid & 1;
    const int bm = blockIdx.y * 128, bn = blockIdx.x * 128;

    auto issue = [&](int it) {
        const int st = it % 3;
        const int k0 = it * 32;
        const uint32_t ab = smb + (uint32_t)(st * 2 * LIN_STAGE_H) * 2;
        const uint32_t bb = ab + (uint32_t)LIN_STAGE_H * 2;
#pragma unroll
        for (int i = 0; i < 2; i++) {
            int id = tid + i * 256;
            int row = id >> 2, ch = id & 3;
            uint32_t off = (uint32_t)(row * LSTR + ch * 8) * 2;
            cpa16(ab + off, X + (size_t)(bm + row) * Dc + k0 + ch * 8);
            cpa16(bb + off, W + (size_t)(bn + row) * Dc + k0 + ch * 8);
        }
        CPA_COMMIT();
    };

    float acc[2][8][4];
#pragma unroll
    for (int mt = 0; mt < 2; mt++)
#pragma unroll
        for (int nt = 0; nt < 8; nt++)
#pragma unroll
            for (int c = 0; c < 4; c++) acc[mt][nt][c] = 0.0f;

    const uint32_t a_loff = ((uint32_t)(warpm * 32 + (lane & 15)) * LSTR + ((lane >> 4) << 3)) * 2;
    const uint32_t b_loff = ((uint32_t)(warpn * 64 + (lane & 15)) * LSTR + ((lane >> 4) << 3)) * 2;

    issue(0);
    issue(1);
    for (int it = 0; it < 24; it++) {
        if (it == 23) { CPA_WAIT(0); } else { CPA_WAIT(1); }
        __syncthreads();
        if (it < 22) issue(it + 2);

        const int st = it % 3;
        const uint32_t ab = smb + (uint32_t)(st * 2 * LIN_STAGE_H) * 2 + a_loff;
        const uint32_t bb = smb + (uint32_t)(st * 2 * LIN_STAGE_H + LIN_STAGE_H) * 2 + b_loff;

#pragma unroll
        for (int kc = 0; kc < 2; kc++) {
            uint32_t afr[2][4];
#pragma unroll
            for (int mt = 0; mt < 2; mt++)
                ldsm4(afr[mt][0], afr[mt][1], afr[mt][2], afr[mt][3],
                      ab + ((uint32_t)(mt * 16 * LSTR + kc * 16) << 1));
#pragma unroll
            for (int ntp = 0; ntp < 4; ntp++) {
                uint32_t m0, m1, m2, m3;
                ldsm4(m0, m1, m2, m3, bb + ((uint32_t)(ntp * 16 * LSTR + kc * 16) << 1));
                uint32_t b0[2] = {m0, m2}, b1[2] = {m1, m3};
#pragma unroll
                for (int mt = 0; mt < 2; mt++) {
                    mma16(acc[mt][2 * ntp],     afr[mt], b0);
                    mma16(acc[mt][2 * ntp + 1], afr[mt], b1);
                }
            }
        }
    }

#pragma unroll
    for (int mt = 0; mt < 2; mt++) {
        const int row0 = bm + warpm * 32 + mt * 16 + g;
#pragma unroll
        for (int nt = 0; nt < 8; nt++) {
            const int col = bn + warpn * 64 + nt * 8 + 2 * tig;
            const float bx = bias[col], by = bias[col + 1];
            *(uint32_t*)&Y[(size_t)row0 * Dc + col] =
                h2pack(acc[mt][nt][0] + bx, acc[mt][nt][1] + by);
            *(uint32_t*)&Y[(size_t)(row0 + 8) * Dc + col] =
                h2pack(acc[mt][nt][2] + bx, acc[mt][nt][3] + by);
        }
    }
}

// ----------------------------------------------------------------------------
// Flash attention (fp16 m16n8k16): fixed-shift softmax (no max/sum reductions),
// l accumulated via ones-column of V inside the PV MMA.
// CTA = (b, h, 128-query tile), 256 threads = 8 warps x 16 q-rows.
// ----------------------------------------------------------------------------
#define KT 64
#define NT 32
#define KSTR 136
#define VSTR 72
#define KS_H 0
#define VS_H (4 * 64 * KSTR)
#define MS_B ((VS_H + 4 * 64 * VSTR) * 2)
#define ATT_SMEM (MS_B + 4 * 64 * 4)   // 107520 B

__global__ __launch_bounds__(256, 2) void attn_tc(
    float* __restrict__ out)
{
    extern __shared__ __align__(16) __half smh[];
    const uint32_t smb = smem_u32(smh);
    float* msf = (float*)((char*)smh + MS_B);

    const int tid = threadIdx.x;
    const int wid = tid >> 5, lane = tid & 31;
    const int g = lane >> 2, tig = lane & 3;

    const int b = blockIdx.z, h = blockIdx.y, q0 = blockIdx.x * 128;
    const int hoff = h * HDc;

    auto issue_tile = [&](int t) {
        const int s = t & 3;
        const size_t rb = (size_t)(b * Sc + t * KT) * Dc + hoff;
        const __half* gk  = g_k  + rb;
        const __half* glk = g_lk + rb;
        const __half* gv  = g_v  + rb;
        const uint32_t ksb = smb + (uint32_t)(KS_H + s * 64 * KSTR) * 2;
        const uint32_t vsb = smb + (uint32_t)(VS_H + s * 64 * VSTR) * 2;
#pragma unroll
        for (int i = 0; i < 4; i++) {
            int id = tid + i * 256;
            int row = id >> 4, ch = id & 15;
            const __half* src = (ch < 8) ? (gk + (size_t)row * Dc + ch * 8)
                                         : (glk + (size_t)row * Dc + (ch - 8) * 8);
            cpa16(ksb + (uint32_t)(row * KSTR + ch * 8) * 2, src);
        }
#pragma unroll
        for (int i = 0; i < 2; i++) {
            int id = tid + i * 256;
            int row = id >> 3, ch = id & 7;
            cpa16(vsb + (uint32_t)(row * VSTR + ch * 8) * 2, gv + (size_t)row * Dc + ch * 8);
        }
        if (tid < 16)
            cpa16(smb + (uint32_t)MS_B + (uint32_t)(s * 64 + tid * 4) * 4,
                  g_mkl + (size_t)b * Sc + t * KT + tid * 4);
        CPA_COMMIT();
    };

    // ---- Q staging into KS bufs 0+1, then -> registers
    {
        const size_t rb = (size_t)(b * Sc + q0) * Dc + hoff;
#pragma unroll
        for (int i = 0; i < 8; i++) {
            int id = tid + i * 256;
            int row = id >> 4, ch = id & 15;
            const __half* src = (ch < 8) ? (g_q + rb + (size_t)row * Dc + ch * 8)
                                         : (g_lq + rb + (size_t)row * Dc + (ch - 8) * 8);
            cpa16(smb + (uint32_t)(row * KSTR + ch * 8) * 2, src);
        }
        CPA_COMMIT();
    }
    // ones-column init: V dims 64-71 = {1,0,...,0} in all 4 ring buffers.
    // cp.async only ever writes dims 0-63, so this survives the whole loop.
    {
        int buf = tid >> 6, key = tid & 63;
        uint4* p = (uint4*)((char*)smh +
            ((size_t)(VS_H + buf * 64 * VSTR + key * VSTR + 64) * 2));
        *p = make_uint4(0x00003C00u, 0u, 0u, 0u);   // half2(1.0, 0.0), zeros
    }
    CPA_WAIT(0);
    __syncthreads();

    uint32_t qa[8][4];
    {
        const uint32_t qlane = smb +
            ((uint32_t)((wid * 16 + (lane & 15)) * KSTR + ((lane >> 4) << 3)) << 1);
#pragma unroll
        for (int kc = 0; kc < 8; kc++)
            ldsm4(qa[kc][0], qa[kc][1], qa[kc][2], qa[kc][3],
                  qlane + ((uint32_t)(kc * 16) << 1));
    }
    __syncthreads();
    issue_tile(0);

    float oacc[8][4];
    float oacc2[4];            // ones-column accumulator (l lives in col 64)
    uint32_t pold[4][4];
#pragma unroll
    for (int nt = 0; nt < 8; nt++)
#pragma unroll
        for (int c = 0; c < 4; c++) oacc[nt][c] = 0.0f;
#pragma unroll
    for (int c = 0; c < 4; c++) oacc2[c] = 0.0f;
#pragma unroll
    for (int kb = 0; kb < 4; kb++)
#pragma unroll
        for (int c = 0; c < 4; c++) pold[kb][c] = 0u;

    const uint32_t k_loff = ((uint32_t)(lane & 15) * KSTR + ((lane >> 4) << 3)) << 1;
    const uint32_t v_loff = ((uint32_t)((lane & 7) + (((lane >> 3) & 1) << 3)) * VSTR
                             + ((lane >> 4) << 3)) << 1;
    const uint32_t v2_loff = ((uint32_t)(lane & 15) * VSTR + 64) << 1;
    const float C1 = 0.18033688011112042f;   // 0.125 * log2(e)

    for (int t = 0; t < NT; t++) {
        if (t < NT - 1) { issue_tile(t + 1); CPA_WAIT(1); }
        else            { CPA_WAIT(0); }
        __syncthreads();

        const int s = t & 3, sp = (t - 1) & 3;
        const uint32_t ksl  = smb + ((uint32_t)(KS_H + s * 64 * KSTR) << 1) + k_loff;
        const uint32_t vsl  = smb + ((uint32_t)(VS_H + sp * 64 * VSTR) << 1) + v_loff;
        const uint32_t vsl2 = smb + ((uint32_t)(VS_H + sp * 64 * VSTR) << 1) + v2_loff;
        const float* ms = msf + s * 64;

        // ---- QK(t)
        float sacc[8][4];
#pragma unroll
        for (int nt = 0; nt < 8; nt++)
#pragma unroll
            for (int c = 0; c < 4; c++) sacc[nt][c] = 0.0f;

#pragma unroll
        for (int kc = 0; kc < 8; kc++) {
#pragma unroll
            for (int nt2 = 0; nt2 < 4; nt2++) {
                uint32_t m0r, m1r, m2r, m3r;
                ldsm4(m0r, m1r, m2r, m3r,
                      ksl + ((uint32_t)(nt2 * 16 * KSTR + kc * 16) << 1));
                uint32_t b0[2] = {m0r, m2r}, b1[2] = {m1r, m3r};
                mma16(sacc[2 * nt2],     qa[kc], b0);
                mma16(sacc[2 * nt2 + 1], qa[kc], b1);
            }
        }

        // ---- PV(t-1): O += P @ V, plus ones-column frag -> l
        if (t > 0) {
#pragma unroll
            for (int kb = 0; kb < 4; kb++) {
#pragma unroll
                for (int nt2 = 0; nt2 < 4; nt2++) {
                    uint32_t m0r, m1r, m2r, m3r;
                    ldsm4t(m0r, m1r, m2r, m3r,
                           vsl + ((uint32_t)(kb * 16 * VSTR + nt2 * 16) << 1));
                    uint32_t b0[2] = {m0r, m1r}, b1[2] = {m2r, m3r};
                    mma16(oacc[2 * nt2],     pold[kb], b0);
                    mma16(oacc[2 * nt2 + 1], pold[kb], b1);
                }
                uint32_t e0, e1;
                ldsm2t(e0, e1, vsl2 + ((uint32_t)(kb * 16 * VSTR) << 1));
                uint32_t be[2] = {e0, e1};
                mma16(oacc2, pold[kb], be);
            }
        }

        // ---- softmax(t): fixed shift, straight-line, no reductions
#pragma unroll
        for (int nt = 0; nt < 8; nt++) {
            const float mk0 = ms[nt * 8 + 2 * tig], mk1 = ms[nt * 8 + 2 * tig + 1];
            sacc[nt][0] = exp2f(sacc[nt][0] * C1 + mk0);
            sacc[nt][1] = exp2f(sacc[nt][1] * C1 + mk1);
            sacc[nt][2] = exp2f(sacc[nt][2] * C1 + mk0);
            sacc[nt][3] = exp2f(sacc[nt][3] * C1 + mk1);
        }
#pragma unroll
        for (int kb = 0; kb < 4; kb++) {
            pold[kb][0] = h2pack(sacc[2 * kb][0],     sacc[2 * kb][1]);
            pold[kb][1] = h2pack(sacc[2 * kb][2],     sacc[2 * kb][3]);
            pold[kb][2] = h2pack(sacc[2 * kb + 1][0], sacc[2 * kb + 1][1]);
            pold[kb][3] = h2pack(sacc[2 * kb + 1][2], sacc[2 * kb + 1][3]);
        }
    }

    // ---- drain: PV(NT-1)
    {
        const int sp = (NT - 1) & 3;
        const uint32_t vsl  = smb + ((uint32_t)(VS_H + sp * 64 * VSTR) << 1) + v_loff;
        const uint32_t vsl2 = smb + ((uint32_t)(VS_H + sp * 64 * VSTR) << 1) + v2_loff;
#pragma unroll
        for (int kb = 0; kb < 4; kb++) {
#pragma unroll
            for (int nt2 = 0; nt2 < 4; nt2++) {
                uint32_t m0r, m1r, m2r, m3r;
                ldsm4t(m0r, m1r, m2r, m3r,
                       vsl + ((uint32_t)(kb * 16 * VSTR + nt2 * 16) << 1));
                uint32_t b0[2] = {m0r, m1r}, b1[2] = {m2r, m3r};
                mma16(oacc[2 * nt2],     pold[kb], b0);
                mma16(oacc[2 * nt2 + 1], pold[kb], b1);
            }
            uint32_t e0, e1;
            ldsm2t(e0, e1, vsl2 + ((uint32_t)(kb * 16 * VSTR) << 1));
            uint32_t be[2] = {e0, e1};
            mma16(oacc2, pold[kb], be);
        }
    }

    // ---- epilogue: l = ones-column (col 64 -> tig==0 lanes, d[0]/d[2])
    const float l0 = __shfl_sync(0xffffffffu, oacc2[0], lane & ~3);
    const float l1 = __shfl_sync(0xffffffffu, oacc2[2], lane & ~3);
    const float i0 = 1.0f / l0, i1 = 1.0f / l1;
    const int row = b * Sc + q0 + wid * 16 + g;
    float* ob = out + (size_t)row * Dc + hoff;
#pragma unroll
    for (int nt = 0; nt < 8; nt++) {
        const int col = nt * 8 + 2 * tig;
        *(float2*)&ob[col] = make_float2(oacc[nt][0] * i0, oacc[nt][1] * i0);
        *(float2*)&ob[(size_t)8 * Dc + col] = make_float2(oacc[nt][2] * i1, oacc[nt][3] * i1);
    }
}

// ----------------------------------------------------------------------------
// Launch
// ----------------------------------------------------------------------------
extern "C" void kernel_launch(void* const* d_in, const int* in_sizes, int n_in,
                              void* d_out, int out_size)
{
    const float* hs   = (const float*)d_in[0];
    const float* lq   = (const float*)d_in[1];
    const float* lk   = (const float*)d_in[2];
    const float* mask = (const float*)d_in[3];
    const float* Wq   = (const float*)d_in[4];
    const float* bq   = (const float*)d_in[5];
    const float* Wk   = (const float*)d_in[6];
    const float* bk   = (const float*)d_in[7];
    const float* Wv   = (const float*)d_in[8];
    const float* bv   = (const float*)d_in[9];
    float* out = (float*)d_out;

    dim3 gp(512, 7);
    round_all<<<gp, 256>>>(hs, lq, lk, Wq, Wk, Wv, mask);

    cudaFuncSetAttribute(linear_tc, cudaFuncAttributeMaxDynamicSharedMemorySize, LIN_SMEM);
    dim3 gl(Dc / 128, Mrows / 128, 3);   // (6, 64, 3)
    linear_tc<<<gl, 256, LIN_SMEM>>>(bq, bk, bv);

    cudaFuncSetAttribute(attn_tc, cudaFuncAttributeMaxDynamicSharedMemorySize, ATT_SMEM);
    dim3 ga(Sc / 128, Hc, Bc);           // (16, 12, 4)
    attn_tc<<<ga, 256, ATT_SMEM>>>(out);
}

// round 12
// speedup vs baseline: 2.4010x; 1.0178x over previous
#include <cuda_runtime.h>
#include <cuda_fp16.h>
#include <cstdint>

// ----------------------------------------------------------------------------
// Problem constants
// ----------------------------------------------------------------------------
#define Bc   4
#define Sc   2048
#define Dc   768
#define Hc   12
#define HDc  64
#define Mrows (Bc * Sc)   // 8192

// Scratch (device globals)
__device__ __half g_q [(size_t)Mrows * Dc];
__device__ __half g_k [(size_t)Mrows * Dc];
__device__ __half g_v [(size_t)Mrows * Dc];
__device__ __half g_hs[(size_t)Mrows * Dc];
__device__ __half g_lq[(size_t)Mrows * Dc];
__device__ __half g_lk[(size_t)Mrows * Dc];
__device__ __half g_wq[(size_t)Dc * Dc];
__device__ __half g_wk[(size_t)Dc * Dc];
__device__ __half g_wv[(size_t)Dc * Dc];
__device__ float  g_mkl[(size_t)Bc * Sc];   // mask * log2(e) - 8

// ----------------------------------------------------------------------------
// Helpers
// ----------------------------------------------------------------------------
__device__ __forceinline__ uint32_t smem_u32(const void* p) {
    uint32_t a;
    asm("{ .reg .u64 t; cvta.to.shared.u64 t, %1; cvt.u32.u64 %0, t; }" : "=r"(a) : "l"(p));
    return a;
}
__device__ __forceinline__ void cpa16(uint32_t dst, const void* src) {
    asm volatile("cp.async.cg.shared.global [%0], [%1], 16;" :: "r"(dst), "l"(src));
}
#define CPA_COMMIT() asm volatile("cp.async.commit_group;" ::: "memory")
#define CPA_WAIT(N)  asm volatile("cp.async.wait_group %0;" :: "n"(N) : "memory")

__device__ __forceinline__ float ex2(float x) {
    float r;
    asm("ex2.approx.f32 %0, %1;" : "=f"(r) : "f"(x));
    return r;
}

__device__ __forceinline__ void ldsm4(uint32_t& r0, uint32_t& r1, uint32_t& r2, uint32_t& r3,
                                      uint32_t addr) {
    asm volatile("ldmatrix.sync.aligned.m8n8.x4.shared.b16 {%0,%1,%2,%3}, [%4];"
                 : "=r"(r0), "=r"(r1), "=r"(r2), "=r"(r3) : "r"(addr));
}
__device__ __forceinline__ void ldsm4t(uint32_t& r0, uint32_t& r1, uint32_t& r2, uint32_t& r3,
                                       uint32_t addr) {
    asm volatile("ldmatrix.sync.aligned.m8n8.x4.trans.shared.b16 {%0,%1,%2,%3}, [%4];"
                 : "=r"(r0), "=r"(r1), "=r"(r2), "=r"(r3) : "r"(addr));
}
__device__ __forceinline__ void ldsm2t(uint32_t& r0, uint32_t& r1, uint32_t addr) {
    asm volatile("ldmatrix.sync.aligned.m8n8.x2.trans.shared.b16 {%0,%1}, [%2];"
                 : "=r"(r0), "=r"(r1) : "r"(addr));
}

// d += a @ b  (m16n8k16, fp16 inputs, f32 accum)
__device__ __forceinline__ void mma16(float* d, const uint32_t* a, const uint32_t* b) {
    asm volatile(
        "mma.sync.aligned.m16n8k16.row.col.f32.f16.f16.f32 "
        "{%0,%1,%2,%3}, {%4,%5,%6,%7}, {%8,%9}, {%0,%1,%2,%3};\n"
        : "+f"(d[0]), "+f"(d[1]), "+f"(d[2]), "+f"(d[3])
        : "r"(a[0]), "r"(a[1]), "r"(a[2]), "r"(a[3]), "r"(b[0]), "r"(b[1]));
}

__device__ __forceinline__ uint32_t h2pack(float a, float b) {
    __half2 h = __floats2half2_rn(a, b);
    return *reinterpret_cast<uint32_t*>(&h);
}

// ----------------------------------------------------------------------------
// Prep: f32 -> fp16 for six arrays; mask -> mask*log2(e) - 8
// ----------------------------------------------------------------------------
__global__ void round_all(const float* __restrict__ hs, const float* __restrict__ lq,
                          const float* __restrict__ lk, const float* __restrict__ wq,
                          const float* __restrict__ wk, const float* __restrict__ wv,
                          const float* __restrict__ mask)
{
    const int which = blockIdx.y;
    int i = blockIdx.x * blockDim.x + threadIdx.x;
    int stride = gridDim.x * blockDim.x;

    if (which == 6) {
        const float L2E = 1.4426950408889634f;
        const int n4 = (Bc * Sc) / 4;
        for (; i < n4; i += stride) {
            float4 v = ((const float4*)mask)[i];
            v.x = v.x * L2E - 8.0f; v.y = v.y * L2E - 8.0f;
            v.z = v.z * L2E - 8.0f; v.w = v.w * L2E - 8.0f;
            ((float4*)g_mkl)[i] = v;
        }
        return;
    }

    const float* s;
    __half* d;
    int n8;
    if (which == 0)      { s = hs; d = g_hs; n8 = (Mrows * Dc) / 8; }
    else if (which == 1) { s = lq; d = g_lq; n8 = (Mrows * Dc) / 8; }
    else if (which == 2) { s = lk; d = g_lk; n8 = (Mrows * Dc) / 8; }
    else if (which == 3) { s = wq; d = g_wq; n8 = (Dc * Dc) / 8; }
    else if (which == 4) { s = wk; d = g_wk; n8 = (Dc * Dc) / 8; }
    else                 { s = wv; d = g_wv; n8 = (Dc * Dc) / 8; }

    for (; i < n8; i += stride) {
        float4 v0 = ((const float4*)s)[2 * i];
        float4 v1 = ((const float4*)s)[2 * i + 1];
        uint4 o;
        o.x = h2pack(v0.x, v0.y);
        o.y = h2pack(v0.z, v0.w);
        o.z = h2pack(v1.x, v1.y);
        o.w = h2pack(v1.z, v1.w);
        ((uint4*)d)[i] = o;
    }
}

// ----------------------------------------------------------------------------
// Linear: Y = X @ W^T + b  (fp16 m16n8k16 + ldmatrix, 128x128x32)
// 3-stage cp.async pipeline, one __syncthreads per k-iter. (verified R9/R10)
// ----------------------------------------------------------------------------
#define LSTR 40
#define LIN_STAGE_H (128 * LSTR)
#define LIN_SMEM (6 * LIN_STAGE_H * 2)           // 61440 B

__global__ __launch_bounds__(256, 2) void linear_tc(
    const float* __restrict__ bq,
    const float* __restrict__ bk,
    const float* __restrict__ bv)
{
    extern __shared__ __align__(16) __half smh[];
    const uint32_t smb = smem_u32(smh);

    const int z = blockIdx.z;
    const __half* X    = g_hs;
    const __half* W    = (z == 0) ? g_wq : (z == 1) ? g_wk : g_wv;
    const float* bias  = (z == 0) ? bq   : (z == 1) ? bk   : bv;
    __half* Y          = (z == 0) ? g_q  : (z == 1) ? g_k  : g_v;

    const int tid = threadIdx.x;
    const int wid = tid >> 5, lane = tid & 31;
    const int g = lane >> 2, tig = lane & 3;
    const int warpm = wid >> 1, warpn = wid & 1;
    const int bm = blockIdx.y * 128, bn = blockIdx.x * 128;

    auto issue = [&](int it) {
        const int st = it % 3;
        const int k0 = it * 32;
        const uint32_t ab = smb + (uint32_t)(st * 2 * LIN_STAGE_H) * 2;
        const uint32_t bb = ab + (uint32_t)LIN_STAGE_H * 2;
#pragma unroll
        for (int i = 0; i < 2; i++) {
            int id = tid + i * 256;
            int row = id >> 2, ch = id & 3;
            uint32_t off = (uint32_t)(row * LSTR + ch * 8) * 2;
            cpa16(ab + off, X + (size_t)(bm + row) * Dc + k0 + ch * 8);
            cpa16(bb + off, W + (size_t)(bn + row) * Dc + k0 + ch * 8);
        }
        CPA_COMMIT();
    };

    float acc[2][8][4];
#pragma unroll
    for (int mt = 0; mt < 2; mt++)
#pragma unroll
        for (int nt = 0; nt < 8; nt++)
#pragma unroll
            for (int c = 0; c < 4; c++) acc[mt][nt][c] = 0.0f;

    const uint32_t a_loff = ((uint32_t)(warpm * 32 + (lane & 15)) * LSTR + ((lane >> 4) << 3)) * 2;
    const uint32_t b_loff = ((uint32_t)(warpn * 64 + (lane & 15)) * LSTR + ((lane >> 4) << 3)) * 2;

    issue(0);
    issue(1);
    for (int it = 0; it < 24; it++) {
        if (it == 23) { CPA_WAIT(0); } else { CPA_WAIT(1); }
        __syncthreads();
        if (it < 22) issue(it + 2);

        const int st = it % 3;
        const uint32_t ab = smb + (uint32_t)(st * 2 * LIN_STAGE_H) * 2 + a_loff;
        const uint32_t bb = smb + (uint32_t)(st * 2 * LIN_STAGE_H + LIN_STAGE_H) * 2 + b_loff;

#pragma unroll
        for (int kc = 0; kc < 2; kc++) {
            uint32_t afr[2][4];
#pragma unroll
            for (int mt = 0; mt < 2; mt++)
                ldsm4(afr[mt][0], afr[mt][1], afr[mt][2], afr[mt][3],
                      ab + ((uint32_t)(mt * 16 * LSTR + kc * 16) << 1));
#pragma unroll
            for (int ntp = 0; ntp < 4; ntp++) {
                uint32_t m0, m1, m2, m3;
                ldsm4(m0, m1, m2, m3, bb + ((uint32_t)(ntp * 16 * LSTR + kc * 16) << 1));
                uint32_t b0[2] = {m0, m2}, b1[2] = {m1, m3};
#pragma unroll
                for (int mt = 0; mt < 2; mt++) {
                    mma16(acc[mt][2 * ntp],     afr[mt], b0);
                    mma16(acc[mt][2 * ntp + 1], afr[mt], b1);
                }
            }
        }
    }

#pragma unroll
    for (int mt = 0; mt < 2; mt++) {
        const int row0 = bm + warpm * 32 + mt * 16 + g;
#pragma unroll
        for (int nt = 0; nt < 8; nt++) {
            const int col = bn + warpn * 64 + nt * 8 + 2 * tig;
            const float bx = bias[col], by = bias[col + 1];
            *(uint32_t*)&Y[(size_t)row0 * Dc + col] =
                h2pack(acc[mt][nt][0] + bx, acc[mt][nt][1] + by);
            *(uint32_t*)&Y[(size_t)(row0 + 8) * Dc + col] =
                h2pack(acc[mt][nt][2] + bx, acc[mt][nt][3] + by);
        }
    }
}

// ----------------------------------------------------------------------------
// Flash attention (fp16 m16n8k16): fixed-shift softmax, ones-column l.
// 32 q-rows per warp (halves K/V smem duplication). CTA = (b, h, 256-q tile),
// 256 threads = 8 warps x 32 q-rows, KT=32, occupancy 1.
// ----------------------------------------------------------------------------
#define KT 32
#define NT 64                           // Sc / KT
#define KSTR 136
#define VSTR 72
#define KSBUF (KT * KSTR)               // 4352 halfs
#define VSBUF (KT * VSTR)               // 2304 halfs
#define KS_H 0                          // 4 bufs
#define VS_H (4 * KSBUF)                // 17408
#define MS_B ((VS_H + 4 * VSBUF) * 2)   // 53248 bytes
#define QS_B (MS_B + 4 * KT * 4)        // 53760 bytes (Q staging region)
#define ATT_SMEM (QS_B + 256 * KSTR * 2)  // 123392 B

__global__ __launch_bounds__(256, 1) void attn_tc(
    float* __restrict__ out)
{
    extern __shared__ __align__(16) __half smh[];
    const uint32_t smb = smem_u32(smh);
    float* msf = (float*)((char*)smh + MS_B);

    const int tid = threadIdx.x;
    const int wid = tid >> 5, lane = tid & 31;
    const int g = lane >> 2, tig = lane & 3;

    const int b = blockIdx.z, h = blockIdx.y, q0 = blockIdx.x * 256;
    const int hoff = h * HDc;

    auto issue_tile = [&](int t) {
        const int s = t & 3;
        const size_t rb = (size_t)(b * Sc + t * KT) * Dc + hoff;
        const __half* gk  = g_k  + rb;
        const __half* glk = g_lk + rb;
        const __half* gv  = g_v  + rb;
        const uint32_t ksb = smb + (uint32_t)(KS_H + s * KSBUF) * 2;
        const uint32_t vsb = smb + (uint32_t)(VS_H + s * VSBUF) * 2;
        // KS: 32 rows x 16 chunks  (512 cpa16, 2/thread)
#pragma unroll
        for (int i = 0; i < 2; i++) {
            int id = tid + i * 256;
            int row = id >> 4, ch = id & 15;
            const __half* src = (ch < 8) ? (gk + (size_t)row * Dc + ch * 8)
                                         : (glk + (size_t)row * Dc + (ch - 8) * 8);
            cpa16(ksb + (uint32_t)(row * KSTR + ch * 8) * 2, src);
        }
        // VS: 32 rows x 8 chunks (256 cpa16, 1/thread)
        {
            int row = tid >> 3, ch = tid & 7;
            cpa16(vsb + (uint32_t)(row * VSTR + ch * 8) * 2, gv + (size_t)row * Dc + ch * 8);
        }
        if (tid < 8)
            cpa16(smb + (uint32_t)MS_B + (uint32_t)(s * KT + tid * 4) * 4,
                  g_mkl + (size_t)b * Sc + t * KT + tid * 4);
        CPA_COMMIT();
    };

    // ---- Q staging (separate region, survives whole kernel)
    {
        const size_t rb = (size_t)(b * Sc + q0) * Dc + hoff;
#pragma unroll
        for (int i = 0; i < 16; i++) {
            int id = tid + i * 256;
            int row = id >> 4, ch = id & 15;
            const __half* src = (ch < 8) ? (g_q + rb + (size_t)row * Dc + ch * 8)
                                         : (g_lq + rb + (size_t)row * Dc + (ch - 8) * 8);
            cpa16(smb + (uint32_t)QS_B + (uint32_t)(row * KSTR + ch * 8) * 2, src);
        }
        CPA_COMMIT();
    }
    // ones-column init: V dims 64-71 = {1,0,...} in all 4 ring bufs (never
    // overwritten: cp.async only touches dims 0-63). 4 bufs x 32 keys = 128.
    if (tid < 128) {
        int buf = tid >> 5, key = tid & 31;
        uint4* p = (uint4*)((char*)smh +
            ((size_t)(VS_H + buf * VSBUF + key * VSTR + 64) * 2));
        *p = make_uint4(0x00003C00u, 0u, 0u, 0u);
    }
    issue_tile(0);

    // ---- Q fragments -> registers (32 rows/warp: two 16-row frags per kc)
    CPA_WAIT(1);            // Q-staging group complete (tile0 may be in flight)
    __syncthreads();
    uint32_t qa[8][2][4];
    {
        const uint32_t qlane = smb + (uint32_t)QS_B +
            ((uint32_t)((wid * 32 + (lane & 15)) * KSTR + ((lane >> 4) << 3)) << 1);
#pragma unroll
        for (int kc = 0; kc < 8; kc++) {
            ldsm4(qa[kc][0][0], qa[kc][0][1], qa[kc][0][2], qa[kc][0][3],
                  qlane + ((uint32_t)(kc * 16) << 1));
            ldsm4(qa[kc][1][0], qa[kc][1][1], qa[kc][1][2], qa[kc][1][3],
                  qlane + ((uint32_t)(16 * KSTR + kc * 16) << 1));
        }
    }

    float oacc[2][8][4];
    float oacc2[2][4];
    uint32_t pold[2][2][4];   // [kb][mt][4]
#pragma unroll
    for (int mt = 0; mt < 2; mt++) {
#pragma unroll
        for (int nt = 0; nt < 8; nt++)
#pragma unroll
            for (int c = 0; c < 4; c++) oacc[mt][nt][c] = 0.0f;
#pragma unroll
        for (int c = 0; c < 4; c++) oacc2[mt][c] = 0.0f;
#pragma unroll
        for (int kb = 0; kb < 2; kb++)
#pragma unroll
            for (int c = 0; c < 4; c++) pold[kb][mt][c] = 0u;
    }

    const uint32_t k_loff = ((uint32_t)(lane & 15) * KSTR + ((lane >> 4) << 3)) << 1;
    const uint32_t v_loff = ((uint32_t)((lane & 7) + (((lane >> 3) & 1) << 3)) * VSTR
                             + ((lane >> 4) << 3)) << 1;
    const uint32_t v2_loff = ((uint32_t)(lane & 15) * VSTR + 64) << 1;
    const float C1 = 0.18033688011112042f;   // 0.125 * log2(e)

    for (int t = 0; t < NT; t++) {
        if (t < NT - 1) { issue_tile(t + 1); CPA_WAIT(1); }
        else            { CPA_WAIT(0); }
        __syncthreads();

        const int s = t & 3, sp = (t - 1) & 3;
        const uint32_t ksl  = smb + ((uint32_t)(KS_H + s * KSBUF) << 1) + k_loff;
        const uint32_t vsl  = smb + ((uint32_t)(VS_H + sp * VSBUF) << 1) + v_loff;
        const uint32_t vsl2 = smb + ((uint32_t)(VS_H + sp * VSBUF) << 1) + v2_loff;
        const float* ms = msf + s * KT;

        // ---- QK(t): 32q x 32k x 128d  (64 mma16, 16 ldsm4)
        float sacc[2][4][4];
#pragma unroll
        for (int mt = 0; mt < 2; mt++)
#pragma unroll
            for (int nt = 0; nt < 4; nt++)
#pragma unroll
                for (int c = 0; c < 4; c++) sacc[mt][nt][c] = 0.0f;

#pragma unroll
        for (int kc = 0; kc < 8; kc++) {
#pragma unroll
            for (int nt2 = 0; nt2 < 2; nt2++) {
                uint32_t m0r, m1r, m2r, m3r;
                ldsm4(m0r, m1r, m2r, m3r,
                      ksl + ((uint32_t)(nt2 * 16 * KSTR + kc * 16) << 1));
                uint32_t b0[2] = {m0r, m2r}, b1[2] = {m1r, m3r};
#pragma unroll
                for (int mt = 0; mt < 2; mt++) {
                    mma16(sacc[mt][2 * nt2],     qa[kc][mt], b0);
                    mma16(sacc[mt][2 * nt2 + 1], qa[kc][mt], b1);
                }
            }
        }

        // ---- PV(t-1): O += P @ V (V frags shared across both row-halves)
        if (t > 0) {
#pragma unroll
            for (int kb = 0; kb < 2; kb++) {
#pragma unroll
                for (int nt2 = 0; nt2 < 4; nt2++) {
                    uint32_t m0r, m1r, m2r, m3r;
                    ldsm4t(m0r, m1r, m2r, m3r,
                           vsl + ((uint32_t)(kb * 16 * VSTR + nt2 * 16) << 1));
                    uint32_t b0[2] = {m0r, m1r}, b1[2] = {m2r, m3r};
#pragma unroll
                    for (int mt = 0; mt < 2; mt++) {
                        mma16(oacc[mt][2 * nt2],     pold[kb][mt], b0);
                        mma16(oacc[mt][2 * nt2 + 1], pold[kb][mt], b1);
                    }
                }
                uint32_t e0, e1;
                ldsm2t(e0, e1, vsl2 + ((uint32_t)(kb * 16 * VSTR) << 1));
                uint32_t be[2] = {e0, e1};
#pragma unroll
                for (int mt = 0; mt < 2; mt++)
                    mma16(oacc2[mt], pold[kb][mt], be);
            }
        }

        // ---- softmax(t): fixed shift, straight-line (EX2 via inline PTX)
#pragma unroll
        for (int mt = 0; mt < 2; mt++)
#pragma unroll
            for (int nt = 0; nt < 4; nt++) {
                const float mk0 = ms[nt * 8 + 2 * tig], mk1 = ms[nt * 8 + 2 * tig + 1];
                sacc[mt][nt][0] = ex2(sacc[mt][nt][0] * C1 + mk0);
                sacc[mt][nt][1] = ex2(sacc[mt][nt][1] * C1 + mk1);
                sacc[mt][nt][2] = ex2(sacc[mt][nt][2] * C1 + mk0);
                sacc[mt][nt][3] = ex2(sacc[mt][nt][3] * C1 + mk1);
            }
#pragma unroll
        for (int kb = 0; kb < 2; kb++)
#pragma unroll
            for (int mt = 0; mt < 2; mt++) {
                pold[kb][mt][0] = h2pack(sacc[mt][2 * kb][0],     sacc[mt][2 * kb][1]);
                pold[kb][mt][1] = h2pack(sacc[mt][2 * kb][2],     sacc[mt][2 * kb][3]);
                pold[kb][mt][2] = h2pack(sacc[mt][2 * kb + 1][0], sacc[mt][2 * kb + 1][1]);
                pold[kb][mt][3] = h2pack(sacc[mt][2 * kb + 1][2], sacc[mt][2 * kb + 1][3]);
            }
    }

    // ---- drain: PV(NT-1)
    {
        const int sp = (NT - 1) & 3;
        const uint32_t vsl  = smb + ((uint32_t)(VS_H + sp * VSBUF) << 1) + v_loff;
        const uint32_t vsl2 = smb + ((uint32_t)(VS_H + sp * VSBUF) << 1) + v2_loff;
#pragma unroll
        for (int kb = 0; kb < 2; kb++) {
#pragma unroll
            for (int nt2 = 0; nt2 < 4; nt2++) {
                uint32_t m0r, m1r, m2r, m3r;
                ldsm4t(m0r, m1r, m2r, m3r,
                       vsl + ((uint32_t)(kb * 16 * VSTR + nt2 * 16) << 1));
                uint32_t b0[2] = {m0r, m1r}, b1[2] = {m2r, m3r};
#pragma unroll
                for (int mt = 0; mt < 2; mt++) {
                    mma16(oacc[mt][2 * nt2],     pold[kb][mt], b0);
                    mma16(oacc[mt][2 * nt2 + 1], pold[kb][mt], b1);
                }
            }
            uint32_t e0, e1;
            ldsm2t(e0, e1, vsl2 + ((uint32_t)(kb * 16 * VSTR) << 1));
            uint32_t be[2] = {e0, e1};
#pragma unroll
            for (int mt = 0; mt < 2; mt++)
                mma16(oacc2[mt], pold[kb][mt], be);
        }
    }

    // ---- epilogue: l in ones-column (col 64 lives in tig==0 lanes d[0]/d[2])
#pragma unroll
    for (int mt = 0; mt < 2; mt++) {
        const float l0 = __shfl_sync(0xffffffffu, oacc2[mt][0], lane & ~3);
        const float l1 = __shfl_sync(0xffffffffu, oacc2[mt][2], lane & ~3);
        const float i0 = 1.0f / l0, i1 = 1.0f / l1;
        const int row = b * Sc + q0 + wid * 32 + mt * 16 + g;
        float* ob = out + (size_t)row * Dc + hoff;
#pragma unroll
        for (int nt = 0; nt < 8; nt++) {
            const int col = nt * 8 + 2 * tig;
            *(float2*)&ob[col] = make_float2(oacc[mt][nt][0] * i0, oacc[mt][nt][1] * i0);
            *(float2*)&ob[(size_t)8 * Dc + col] =
                make_float2(oacc[mt][nt][2] * i1, oacc[mt][nt][3] * i1);
        }
    }
}

// ----------------------------------------------------------------------------
// Launch
// ----------------------------------------------------------------------------
extern "C" void kernel_launch(void* const* d_in, const int* in_sizes, int n_in,
                              void* d_out, int out_size)
{
    const float* hs   = (const float*)d_in[0];
    const float* lq   = (const float*)d_in[1];
    const float* lk   = (const float*)d_in[2];
    const float* mask = (const float*)d_in[3];
    const float* Wq   = (const float*)d_in[4];
    const float* bq   = (const float*)d_in[5];
    const float* Wk   = (const float*)d_in[6];
    const float* bk   = (const float*)d_in[7];
    const float* Wv   = (const float*)d_in[8];
    const float* bv   = (const float*)d_in[9];
    float* out = (float*)d_out;

    dim3 gp(512, 7);
    round_all<<<gp, 256>>>(hs, lq, lk, Wq, Wk, Wv, mask);

    cudaFuncSetAttribute(linear_tc, cudaFuncAttributeMaxDynamicSharedMemorySize, LIN_SMEM);
    dim3 gl(Dc / 128, Mrows / 128, 3);   // (6, 64, 3)
    linear_tc<<<gl, 256, LIN_SMEM>>>(bq, bk, bv);

    cudaFuncSetAttribute(attn_tc, cudaFuncAttributeMaxDynamicSharedMemorySize, ATT_SMEM);
    dim3 ga(Sc / 256, Hc, Bc);           // (8, 12, 4) = 384 CTAs
    attn_tc<<<ga, 256, ATT_SMEM>>>(out);
}